// round 14
// baseline (speedup 1.0000x reference)
#include <cuda_runtime.h>
#include <cuda_fp16.h>
#include <cstdint>
#include <math.h>

#define DEPTH 16
#define NN    65535
#define H     256
#define KIN   768
#define NCOL  1280           // 5 gates * 256 units, col = j*5+g (internal)
#define NCOL3 768            // 3 gates * 256 units, col = j*3+g (leaves)

// ---------------- device scratch (no cudaMalloc allowed) ----------------
__device__ __half g_ehi[(size_t)NN * H];
__device__ __half g_elo[(size_t)NN * H];
__device__ __half g_hhi[(size_t)NN * H];
__device__ __half g_hlo[(size_t)NN * H];
__device__ float  g_c  [(size_t)NN * H];
__device__ __half g_B  [(size_t)NCOL * KIN];   // [col][k], internal
__device__ __half g_B3 [(size_t)NCOL3 * H];    // [col][k], leaves (x-part only)
__device__ float  g_bias[NCOL];
__device__ unsigned g_sync[16];                // tail grid-barrier counters

// ---------------- smem layouts (SW128 swizzled, 128B rows) ----------------
static constexpr int ASTG = 128 * 128;                     // 16384
static constexpr int BSTG = 80 * 128;                      // 10240
static constexpr int OFF_BS_MAIN = 2 * ASTG;               // 32768
static constexpr int SMEM_MAIN   = 2 * (ASTG + BSTG);      // 53248 (x3 CTAs)
static constexpr int B3STG = 96 * 128;                     // 12288
static constexpr int OFF_BS_LEAF = 2 * ASTG;               // 32768
static constexpr int SMEM_LEAF   = 2 * (ASTG + B3STG);     // 57344 (x3 CTAs)
static constexpr int SLST = 32 * 128 + 80 * 128;           // 14336
static constexpr int SMEM_SMALL = 8 * SLST;                // 114688

// ---------------- PTX helpers (baseline sm_80+) ----------------
__device__ __forceinline__ uint32_t smem_to_u32(const void* p) {
    uint32_t a;
    asm("{ .reg .u64 t; cvta.to.shared.u64 t, %1; cvt.u32.u64 %0, t; }" : "=r"(a) : "l"(p));
    return a;
}
__device__ __forceinline__ uint32_t swz(uint32_t row, uint32_t segbyte) {
    return row * 128 + (segbyte ^ ((row & 7) << 4));
}
__device__ __forceinline__ void cpasync16(uint32_t dst, const void* src) {
    asm volatile("cp.async.cg.shared.global [%0], [%1], 16;" :: "r"(dst), "l"(src) : "memory");
}
#define CP_COMMIT() asm volatile("cp.async.commit_group;" ::: "memory")
#define CP_WAIT(N)  asm volatile("cp.async.wait_group %0;" :: "n"(N) : "memory")

__device__ __forceinline__ void ldsm4(uint32_t* r, uint32_t addr) {
    asm volatile("ldmatrix.sync.aligned.m8n8.x4.shared.b16 {%0,%1,%2,%3}, [%4];"
        : "=r"(r[0]), "=r"(r[1]), "=r"(r[2]), "=r"(r[3]) : "r"(addr));
}
__device__ __forceinline__ void ldsm2(uint32_t* r, uint32_t addr) {
    asm volatile("ldmatrix.sync.aligned.m8n8.x2.shared.b16 {%0,%1}, [%2];"
        : "=r"(r[0]), "=r"(r[1]) : "r"(addr));
}
__device__ __forceinline__ void mma16816(float* d, const uint32_t* a, const uint32_t* b) {
    asm volatile("mma.sync.aligned.m16n8k16.row.col.f32.f16.f16.f32 "
        "{%0,%1,%2,%3}, {%4,%5,%6,%7}, {%8,%9}, {%0,%1,%2,%3};"
        : "+f"(d[0]), "+f"(d[1]), "+f"(d[2]), "+f"(d[3])
        : "r"(a[0]), "r"(a[1]), "r"(a[2]), "r"(a[3]), "r"(b[0]), "r"(b[1]));
}

__device__ __forceinline__ float sigmoidf_(float x) { return 1.f / (1.f + expf(-x)); }

struct Offs5 { uint32_t a0, a1, b0, b1, b2; };
__device__ __forceinline__ Offs5 make_offs5(int wm, int wn, int lane) {
    Offs5 o;
    const uint32_t sa = (lane >> 4) << 4;
    const uint32_t sb = ((lane >> 3) & 1) << 4;
    o.a0 = swz(wm + (lane & 15), sa);
    o.a1 = swz(wm + 16 + (lane & 15), sa);
    o.b0 = swz(wn + ((lane >> 4) << 3) + (lane & 7), sb);
    o.b1 = swz(wn + 16 + ((lane >> 4) << 3) + (lane & 7), sb);
    o.b2 = swz(wn + 32 + (lane & 7), sb);
    return o;
}
struct Offs6 { uint32_t a0, a1, b0, b1, b2; };
__device__ __forceinline__ Offs6 make_offs6(int wm, int wn, int lane) {
    Offs6 o;
    const uint32_t sa = (lane >> 4) << 4;
    const uint32_t sb = ((lane >> 3) & 1) << 4;
    o.a0 = swz(wm + (lane & 15), sa);
    o.a1 = swz(wm + 16 + (lane & 15), sa);
    o.b0 = swz(wn + ((lane >> 4) << 3) + (lane & 7), sb);
    o.b1 = swz(wn + 16 + ((lane >> 4) << 3) + (lane & 7), sb);
    o.b2 = swz(wn + 32 + ((lane >> 4) << 3) + (lane & 7), sb);
    return o;
}

__device__ __forceinline__ void chunk_mma5(uint32_t abuf, uint32_t bbuf,
                                           const Offs5& o, float acc[2][5][4]) {
#pragma unroll
    for (int k16 = 0; k16 < 4; ++k16) {
        const uint32_t kx = (uint32_t)k16 << 5;
        uint32_t a[2][4], b[5][2], r0[4], r1[4];
        ldsm4(a[0], abuf + (o.a0 ^ kx));
        ldsm4(a[1], abuf + (o.a1 ^ kx));
        ldsm4(r0, bbuf + (o.b0 ^ kx));
        ldsm4(r1, bbuf + (o.b1 ^ kx));
        ldsm2(b[4], bbuf + (o.b2 ^ kx));
        b[0][0] = r0[0]; b[0][1] = r0[1]; b[1][0] = r0[2]; b[1][1] = r0[3];
        b[2][0] = r1[0]; b[2][1] = r1[1]; b[3][0] = r1[2]; b[3][1] = r1[3];
#pragma unroll
        for (int mt = 0; mt < 2; ++mt)
#pragma unroll
            for (int nt = 0; nt < 5; ++nt)
                mma16816(acc[mt][nt], a[mt], b[nt]);
    }
}

__device__ __forceinline__ void chunk_mma6(uint32_t abuf, uint32_t bbuf,
                                           const Offs6& o, float acc[2][6][4]) {
#pragma unroll
    for (int k16 = 0; k16 < 4; ++k16) {
        const uint32_t kx = (uint32_t)k16 << 5;
        uint32_t a[2][4], b[6][2], r0[4], r1[4], r2[4];
        ldsm4(a[0], abuf + (o.a0 ^ kx));
        ldsm4(a[1], abuf + (o.a1 ^ kx));
        ldsm4(r0, bbuf + (o.b0 ^ kx));
        ldsm4(r1, bbuf + (o.b1 ^ kx));
        ldsm4(r2, bbuf + (o.b2 ^ kx));
        b[0][0] = r0[0]; b[0][1] = r0[1]; b[1][0] = r0[2]; b[1][1] = r0[3];
        b[2][0] = r1[0]; b[2][1] = r1[1]; b[3][0] = r1[2]; b[3][1] = r1[3];
        b[4][0] = r2[0]; b[4][1] = r2[1]; b[5][0] = r2[2]; b[5][1] = r2[3];
#pragma unroll
        for (int mt = 0; mt < 2; ++mt)
#pragma unroll
            for (int nt = 0; nt < 6; ++nt)
                mma16816(acc[mt][nt], a[mt], b[nt]);
    }
}

// ---------------- pack kernels ----------------
__global__ void split_emb_kernel(const float* __restrict__ emb) {
    int idx = blockIdx.x * blockDim.x + threadIdx.x;
    if (blockIdx.x == 0 && threadIdx.x < 16) g_sync[threadIdx.x] = 0;   // reset tail barriers
    int stride = gridDim.x * blockDim.x;
    const int total4 = (NN * H) / 4;
    for (int i = idx; i < total4; i += stride) {
        float4 v = reinterpret_cast<const float4*>(emb)[i];
        __half hh[4], hl[4];
        float f[4] = {v.x, v.y, v.z, v.w};
#pragma unroll
        for (int k = 0; k < 4; ++k) {
            hh[k] = __float2half(f[k]);
            hl[k] = __float2half(f[k] - __half2float(hh[k]));
        }
        reinterpret_cast<uint2*>(g_ehi)[i] = *reinterpret_cast<uint2*>(hh);
        reinterpret_cast<uint2*>(g_elo)[i] = *reinterpret_cast<uint2*>(hl);
    }
}

__global__ void pack_w_kernel(
    const float* __restrict__ Wi, const float* __restrict__ bi, const float* __restrict__ Ui,
    const float* __restrict__ Wo, const float* __restrict__ bo, const float* __restrict__ Uo,
    const float* __restrict__ Wu, const float* __restrict__ bu, const float* __restrict__ Uu,
    const float* __restrict__ Wf, const float* __restrict__ bf, const float* __restrict__ Uf)
{
    int idx = blockIdx.x * blockDim.x + threadIdx.x;
    int stride = gridDim.x * blockDim.x;
    if (idx < NCOL) {
        int j = idx / 5, g = idx % 5;
        g_bias[idx] = (g == 0) ? bi[j] : (g == 1) ? bo[j] : (g == 2) ? bu[j] : bf[j];
    }
    for (int e = idx; e < NCOL * KIN; e += stride) {
        int col = e / KIN;
        int k   = e - col * KIN;
        int j = col / 5, g = col % 5;
        float v = 0.f;
        if (k < H) {
            const float* W = (g == 0) ? Wi : (g == 1) ? Wo : (g == 2) ? Wu : Wf;
            v = W[j * H + k];
        } else if (k < 2 * H) {
            int kk = k - H;
            if      (g == 0) v = Ui[j * H + kk];
            else if (g == 1) v = Uo[j * H + kk];
            else if (g == 2) v = Uu[j * H + kk];
            else if (g == 3) v = Uf[j * H + kk];
        } else {
            int kk = k - 2 * H;
            if      (g == 0) v = Ui[H * H + j * H + kk];
            else if (g == 1) v = Uo[H * H + j * H + kk];
            else if (g == 2) v = Uu[H * H + j * H + kk];
            else if (g == 4) v = Uf[H * H + j * H + kk];
        }
        g_B[e] = __float2half(v);
    }
    for (int e = idx; e < NCOL3 * H; e += stride) {
        int col = e / H;
        int k   = e - col * H;
        int j = col / 3, g = col % 3;
        const float* W = (g == 0) ? Wi : (g == 1) ? Wo : Wu;
        g_B3[e] = __float2half(W[j * H + k]);
    }
}

// ---------------- internal level kernel: 128 x 80, KT=64, 2-stage, 3 CTAs/SM ----------------
__global__ void __launch_bounds__(256, 3) hmma_level_kernel(
    int start, int n, float* __restrict__ out)
{
    extern __shared__ char smem[];
    const uint32_t sbase = smem_to_u32(smem);

    const int t    = threadIdx.x;
    const int lane = t & 31;
    const int wid  = t >> 5;
    const int cb   = blockIdx.x;
    const int m0   = blockIdx.y * 128;
    const int gn0  = start + m0;
    const int col0 = cb * 80;

    constexpr int NCH = 24;

    const __half* e_hi = g_ehi + (size_t)gn0 * H;
    const __half* e_lo = g_elo + (size_t)gn0 * H;
    const __half* c1hi = g_hhi + (size_t)(2 * gn0 + 1) * H;
    const __half* c1lo = g_hlo + (size_t)(2 * gn0 + 1) * H;
    const __half* c2hi = g_hhi + (size_t)(2 * gn0 + 2) * H;
    const __half* c2lo = g_hlo + (size_t)(2 * gn0 + 2) * H;

    const int r0 = t >> 3;
    const uint32_t seg8 = (uint32_t)(t & 7) * 8;
    const uint32_t swz0 = swz(r0, (uint32_t)(t & 7) * 16);
    const uint32_t r0H  = (uint32_t)r0 * H;
    const uint32_t r0K  = (uint32_t)r0 * KIN;
    const bool bTail = (t < 128);

    float acc[2][5][4];
#pragma unroll
    for (int mt = 0; mt < 2; ++mt)
#pragma unroll
        for (int nt = 0; nt < 5; ++nt)
#pragma unroll
            for (int r = 0; r < 4; ++r) acc[mt][nt][r] = 0.f;

    auto load_chunk = [&](int c, int st) {
        const int sp  = (c >= 12);
        const int cc  = c - (sp ? 12 : 0);
        const int sec = cc >> 2;
        const uint32_t kof = (uint32_t)(cc & 3) << 6;
        const __half* ab = (sec == 0) ? (sp ? e_lo : e_hi)
                         : (sec == 1) ? (sp ? c1lo : c1hi)
                                      : (sp ? c2lo : c2hi);
        const uint32_t astep = (sec == 0) ? 32u * H : 64u * H;
        const __half* asrc = ab + ((sec == 0) ? r0H : 2 * r0H) + kof + seg8;
        const __half* bsrc = g_B + (size_t)col0 * KIN + cc * 64 + r0K + seg8;
        const uint32_t adst = sbase + st * ASTG + swz0;
        const uint32_t bdst = sbase + OFF_BS_MAIN + st * BSTG + swz0;
        cpasync16(adst +     0, asrc);
        cpasync16(adst +  4096, asrc + astep);
        cpasync16(adst +  8192, asrc + 2 * astep);
        cpasync16(adst + 12288, asrc + 3 * astep);
        cpasync16(bdst +     0, bsrc);
        cpasync16(bdst +  4096, bsrc + 32 * KIN);
        if (bTail) cpasync16(bdst + 8192, bsrc + 64 * KIN);
        CP_COMMIT();
    };

    load_chunk(0, 0);

    const int wm = (wid & 3) * 32;
    const int wn = (wid >> 2) * 40;
    const Offs5 offs = make_offs5(wm, wn, lane);

    for (int c = 0; c < NCH; ++c) {
        const int st = c & 1;
        CP_WAIT(0);
        __syncthreads();
        if (c + 1 < NCH) load_chunk(c + 1, st ^ 1);
        chunk_mma5(sbase + st * ASTG, sbase + OFF_BS_MAIN + st * BSTG, offs, acc);
    }
    __syncthreads();

    float* Cs = reinterpret_cast<float*>(smem);     // [128][84]
#pragma unroll
    for (int mt = 0; mt < 2; ++mt)
#pragma unroll
        for (int nt = 0; nt < 5; ++nt) {
            int m  = wm + mt * 16 + (lane >> 2);
            int nn = wn + nt * 8 + (lane & 3) * 2;
            Cs[m * 84 + nn]           = acc[mt][nt][0];
            Cs[m * 84 + nn + 1]       = acc[mt][nt][1];
            Cs[(m + 8) * 84 + nn]     = acc[mt][nt][2];
            Cs[(m + 8) * 84 + nn + 1] = acc[mt][nt][3];
        }
    __syncthreads();

#pragma unroll
    for (int pass = 0; pass < 8; ++pass) {
        const int task = t + pass * 256;
        const int m = task >> 4;
        const int u = task & 15;
        if (m0 + m >= n) continue;
        const int gn = gn0 + m;
        const int j  = cb * 16 + u;

        const float* cp = &Cs[m * 84 + u * 5];
        float zi = cp[0] + g_bias[j * 5 + 0];
        float zo = cp[1] + g_bias[j * 5 + 1];
        float zu = cp[2] + g_bias[j * 5 + 2];
        float zf0 = cp[3] + g_bias[j * 5 + 3];
        float zf1 = cp[4] + g_bias[j * 5 + 4];
        float vi = sigmoidf_(zi);
        float vo = sigmoidf_(zo);
        float vu = tanhf(zu);
        float cv = vi * vu
                 + sigmoidf_(zf0) * g_c[(size_t)(2 * gn + 1) * H + j]
                 + sigmoidf_(zf1) * g_c[(size_t)(2 * gn + 2) * H + j];
        float h = vo * tanhf(cv);
        __half hh = __float2half(h);
        g_hhi[(size_t)gn * H + j] = hh;
        g_hlo[(size_t)gn * H + j] = __float2half(h - __half2float(hh));
        g_c  [(size_t)gn * H + j] = cv;
        if (out != nullptr && gn == 0) {
            out[j]     = h;
            out[H + j] = cv;
        }
    }
}

// ---------------- leaf kernel: 128 nodes x 96 cols (32 units x 3 gates), K'=512 ----------------
__global__ void __launch_bounds__(256, 3) leaf_kernel(int start, int n)
{
    extern __shared__ char smem[];
    const uint32_t sbase = smem_to_u32(smem);

    const int t    = threadIdx.x;
    const int lane = t & 31;
    const int wid  = t >> 5;
    const int cb   = blockIdx.x;
    const int m0   = blockIdx.y * 128;
    const int gn0  = start + m0;
    const int col0 = cb * 96;

    constexpr int NCH = 8;

    const __half* e_hi = g_ehi + (size_t)gn0 * H;
    const __half* e_lo = g_elo + (size_t)gn0 * H;

    const int r0 = t >> 3;
    const uint32_t seg8 = (uint32_t)(t & 7) * 8;
    const uint32_t swz0 = swz(r0, (uint32_t)(t & 7) * 16);
    const uint32_t r0H  = (uint32_t)r0 * H;

    float acc[2][6][4];
#pragma unroll
    for (int mt = 0; mt < 2; ++mt)
#pragma unroll
        for (int nt = 0; nt < 6; ++nt)
#pragma unroll
            for (int r = 0; r < 4; ++r) acc[mt][nt][r] = 0.f;

    auto load_chunk = [&](int c, int st) {
        const int sp  = (c >= 4);
        const uint32_t kof = (uint32_t)(c & 3) << 6;
        const __half* asrc = (sp ? e_lo : e_hi) + r0H + kof + seg8;
        const __half* bsrc = g_B3 + (size_t)col0 * H + kof + r0H + seg8;
        const uint32_t adst = sbase + st * ASTG + swz0;
        const uint32_t bdst = sbase + OFF_BS_LEAF + st * B3STG + swz0;
        cpasync16(adst +     0, asrc);
        cpasync16(adst +  4096, asrc + 32 * H);
        cpasync16(adst +  8192, asrc + 64 * H);
        cpasync16(adst + 12288, asrc + 96 * H);
        cpasync16(bdst +     0, bsrc);
        cpasync16(bdst +  4096, bsrc + 32 * H);
        cpasync16(bdst +  8192, bsrc + 64 * H);
        CP_COMMIT();
    };

    load_chunk(0, 0);

    const int wm = (wid & 3) * 32;
    const int wn = (wid >> 2) * 48;
    const Offs6 offs = make_offs6(wm, wn, lane);

    for (int c = 0; c < NCH; ++c) {
        const int st = c & 1;
        CP_WAIT(0);
        __syncthreads();
        if (c + 1 < NCH) load_chunk(c + 1, st ^ 1);
        chunk_mma6(sbase + st * ASTG, sbase + OFF_BS_LEAF + st * B3STG, offs, acc);
    }
    __syncthreads();

    float* Cs = reinterpret_cast<float*>(smem);     // [128][100]
#pragma unroll
    for (int mt = 0; mt < 2; ++mt)
#pragma unroll
        for (int nt = 0; nt < 6; ++nt) {
            int m  = wm + mt * 16 + (lane >> 2);
            int nn = wn + nt * 8 + (lane & 3) * 2;
            Cs[m * 100 + nn]           = acc[mt][nt][0];
            Cs[m * 100 + nn + 1]       = acc[mt][nt][1];
            Cs[(m + 8) * 100 + nn]     = acc[mt][nt][2];
            Cs[(m + 8) * 100 + nn + 1] = acc[mt][nt][3];
        }
    __syncthreads();

#pragma unroll
    for (int pass = 0; pass < 16; ++pass) {
        const int task = t + pass * 256;
        const int m = task >> 5;
        const int u = task & 31;
        if (m0 + m >= n) continue;
        const int gn = gn0 + m;
        const int j  = cb * 32 + u;

        const float* cp = &Cs[m * 100 + u * 3];
        float zi = cp[0] + g_bias[j * 5 + 0];
        float zo = cp[1] + g_bias[j * 5 + 1];
        float zu = cp[2] + g_bias[j * 5 + 2];
        float vi = sigmoidf_(zi);
        float vo = sigmoidf_(zo);
        float vu = tanhf(zu);
        float cv = vi * vu;
        float h = vo * tanhf(cv);
        __half hh = __float2half(h);
        g_hhi[(size_t)gn * H + j] = hh;
        g_hlo[(size_t)gn * H + j] = __float2half(h - __half2float(hh));
        g_c  [(size_t)gn * H + j] = cv;
    }
}

// ---------------- fused tail kernel: levels l=LTOP..0, persistent, grid barrier ----------------
// Grid = 128 blocks (always co-resident: 128 <= 148 SMs even at 1 CTA/SM -> no deadlock).
// Each block loops over (cb, mtile) work items per level; split-K smallk tile body.
#define TAIL_GRID 128
#define LTOP 10

__global__ void __launch_bounds__(256, 2) tail_kernel(float* __restrict__ out)
{
    extern __shared__ char smem[];
    const uint32_t sbase = smem_to_u32(smem);

    const int t    = threadIdx.x;
    const int lane = t & 31;
    const int wid  = t >> 5;

    const int ks = wid >> 1;
    const int wn = (wid & 1) * 40;
    constexpr int PER = 6;

    const Offs5 offs = make_offs5(0, wn, lane);

    for (int l = LTOP; l >= 0; --l) {
        const int n = 1 << l;
        const int start = n - 1;
        const int mtiles = (n + 31) / 32;
        const int tiles = 16 * mtiles;

        for (int tile = blockIdx.x; tile < tiles; tile += TAIL_GRID) {
            const int cb = tile & 15;
            const int my = tile >> 4;
            const int m0 = my * 32;
            const int gn0 = start + m0;
            const int col0 = cb * 80;

            __syncthreads();    // previous tile's Cp reads done before stage reuse

            float acc[2][5][4];
#pragma unroll
            for (int mt = 0; mt < 2; ++mt)
#pragma unroll
                for (int nt = 0; nt < 5; ++nt)
#pragma unroll
                    for (int r = 0; r < 4; ++r) acc[mt][nt][r] = 0.f;

            auto load_step = [&](int step, int st) {
#pragma unroll
                for (int i = 0; i < 14; ++i) {
                    int idx = t + i * 256;
                    int sl  = idx / 896;
                    int rem = idx - sl * 896;
                    int c   = sl * PER + step;
                    int kp  = c * 64;
                    int s   = kp / KIN;
                    int k   = kp - s * KIN;
                    uint32_t sbuf = sbase + (sl * 2 + st) * SLST;
                    if (rem < 256) {
                        int row = rem >> 3, seg = rem & 7;
                        const __half* abase;
                        int astride;
                        if (k < H) {
                            abase = (s == 1 ? g_elo : g_ehi) + (size_t)gn0 * H + k;
                            astride = H;
                        } else if (k < 2 * H) {
                            abase = (s == 1 ? g_hlo : g_hhi) + (size_t)(2 * gn0 + 1) * H + (k - H);
                            astride = 2 * H;
                        } else {
                            abase = (s == 1 ? g_hlo : g_hhi) + (size_t)(2 * gn0 + 2) * H + (k - 2 * H);
                            astride = 2 * H;
                        }
                        cpasync16(sbuf + swz(row, seg * 16),
                                  abase + (size_t)row * astride + seg * 8);
                    } else {
                        int r2 = rem - 256;
                        int row = r2 >> 3, seg = r2 & 7;
                        const __half* bbase = g_B + (size_t)col0 * KIN + k;
                        cpasync16(sbuf + 32 * 128 + swz(row, seg * 16),
                                  bbase + (size_t)row * KIN + seg * 8);
                    }
                }
                CP_COMMIT();
            };

            load_step(0, 0);

            for (int step = 0; step < PER; ++step) {
                const int st = step & 1;
                CP_WAIT(0);
                __syncthreads();
                if (step + 1 < PER) load_step(step + 1, st ^ 1);
                const uint32_t abuf = sbase + (ks * 2 + st) * SLST;
                chunk_mma5(abuf, abuf + 32 * 128, offs, acc);
            }
            __syncthreads();

            float* Cp = reinterpret_cast<float*>(smem);   // [4][32][84]
#pragma unroll
            for (int mt = 0; mt < 2; ++mt)
#pragma unroll
                for (int nt = 0; nt < 5; ++nt) {
                    int m  = mt * 16 + (lane >> 2);
                    int nn = wn + nt * 8 + (lane & 3) * 2;
                    float* dst = Cp + ks * (32 * 84);
                    dst[m * 84 + nn]           = acc[mt][nt][0];
                    dst[m * 84 + nn + 1]       = acc[mt][nt][1];
                    dst[(m + 8) * 84 + nn]     = acc[mt][nt][2];
                    dst[(m + 8) * 84 + nn + 1] = acc[mt][nt][3];
                }
            __syncthreads();

#pragma unroll
            for (int pass = 0; pass < 2; ++pass) {
                const int task = t + pass * 256;
                const int m = task >> 4;
                const int u = task & 15;
                if (m0 + m >= n) continue;
                const int gn = gn0 + m;
                const int j  = cb * 16 + u;

                float z[5];
#pragma unroll
                for (int g = 0; g < 5; ++g) {
                    float s = g_bias[j * 5 + g];
#pragma unroll
                    for (int sl = 0; sl < 4; ++sl)
                        s += Cp[sl * (32 * 84) + m * 84 + u * 5 + g];
                    z[g] = s;
                }
                float vi = sigmoidf_(z[0]);
                float vo = sigmoidf_(z[1]);
                float vu = tanhf(z[2]);
                float cv = vi * vu
                         + sigmoidf_(z[3]) * g_c[(size_t)(2 * gn + 1) * H + j]
                         + sigmoidf_(z[4]) * g_c[(size_t)(2 * gn + 2) * H + j];
                float h = vo * tanhf(cv);
                __half hh = __float2half(h);
                g_hhi[(size_t)gn * H + j] = hh;
                g_hlo[(size_t)gn * H + j] = __float2half(h - __half2float(hh));
                g_c  [(size_t)gn * H + j] = cv;
                if (l == 0 && gn == 0) {
                    out[j]     = h;
                    out[H + j] = cv;
                }
            }
        }

        // ---- grid barrier between levels ----
        if (l > 0) {
            __syncthreads();
            if (t == 0) {
                __threadfence();
                atomicAdd(&g_sync[l], 1u);
                while (atomicAdd(&g_sync[l], 0u) < (unsigned)TAIL_GRID) { }
            }
            __syncthreads();
        }
    }
}

// ---------------- host launcher ----------------
extern "C" void kernel_launch(void* const* d_in, const int* in_sizes, int n_in,
                              void* d_out, int out_size)
{
    const float* emb = (const float*)d_in[0];
    const float* Wi  = (const float*)d_in[1];
    const float* bi  = (const float*)d_in[2];
    const float* Ui  = (const float*)d_in[3];
    const float* Wo  = (const float*)d_in[4];
    const float* bo  = (const float*)d_in[5];
    const float* Uo  = (const float*)d_in[6];
    const float* Wu  = (const float*)d_in[7];
    const float* bu  = (const float*)d_in[8];
    const float* Uu  = (const float*)d_in[9];
    const float* Wf  = (const float*)d_in[10];
    const float* bf  = (const float*)d_in[11];
    const float* Uf  = (const float*)d_in[12];

    cudaFuncSetAttribute(hmma_level_kernel, cudaFuncAttributeMaxDynamicSharedMemorySize, SMEM_MAIN);
    cudaFuncSetAttribute(leaf_kernel,       cudaFuncAttributeMaxDynamicSharedMemorySize, SMEM_LEAF);
    cudaFuncSetAttribute(tail_kernel,       cudaFuncAttributeMaxDynamicSharedMemorySize, SMEM_SMALL);

    split_emb_kernel<<<2048, 256>>>(emb);
    pack_w_kernel<<<1024, 256>>>(Wi, bi, Ui, Wo, bo, Uo, Wu, bu, Uu, Wf, bf, Uf);

    // leaves: level 15, n = 32768, 3 gates only
    {
        int n = 1 << (DEPTH - 1);
        int start = n - 1;
        dim3 grid(8, n / 128);
        leaf_kernel<<<grid, 256, SMEM_LEAF>>>(start, n);
    }
    // big internal levels (n >= 2048)
    for (int l = DEPTH - 2; l > LTOP; --l) {
        int n = 1 << l;
        int start = n - 1;
        dim3 grid(16, n / 128);
        hmma_level_kernel<<<grid, 256, SMEM_MAIN>>>(start, n, nullptr);
    }
    // fused tail: levels LTOP..0 in one persistent launch
    tail_kernel<<<TAIL_GRID, 256, SMEM_SMALL>>>((float*)d_out);
}

// round 15
// speedup vs baseline: 1.0136x; 1.0136x over previous
#include <cuda_runtime.h>
#include <cuda_fp16.h>
#include <cstdint>
#include <math.h>

#define DEPTH 16
#define NN    65535
#define H     256
#define KIN   768
#define NCOL  1280           // 5 gates * 256 units, col = j*5+g (internal)
#define NCOL3 768            // 3 gates * 256 units, col = j*3+g (leaves)

// ---------------- device scratch (no cudaMalloc allowed) ----------------
__device__ __half g_ehi[(size_t)NN * H];
__device__ __half g_elo[(size_t)NN * H];
__device__ __half g_hhi[(size_t)NN * H];
__device__ __half g_hlo[(size_t)NN * H];
__device__ float  g_c  [(size_t)NN * H];
__device__ __half g_B  [(size_t)NCOL * KIN];   // [col][k], internal
__device__ __half g_B3 [(size_t)NCOL3 * H];    // [col][k], leaves (x-part only)
__device__ float  g_bias[NCOL];
__device__ unsigned g_sync[16];                // tail grid-barrier counters

// ---------------- smem layouts (SW128 swizzled, 128B rows) ----------------
static constexpr int ASTG = 128 * 128;                     // 16384
static constexpr int BSTG = 80 * 128;                      // 10240
static constexpr int OFF_BS_MAIN = 2 * ASTG;               // 32768
static constexpr int SMEM_MAIN   = 2 * (ASTG + BSTG);      // 53248 (x3 CTAs)
static constexpr int B3STG = 96 * 128;                     // 12288
static constexpr int OFF_BS_LEAF = 2 * ASTG;               // 32768
static constexpr int SMEM_LEAF   = 2 * (ASTG + B3STG);     // 57344 (x3 CTAs)
static constexpr int SLST = 32 * 128 + 80 * 128;           // 14336
static constexpr int SMEM_SMALL = 8 * SLST;                // 114688

// ---------------- PTX helpers (baseline sm_80+) ----------------
__device__ __forceinline__ uint32_t smem_to_u32(const void* p) {
    uint32_t a;
    asm("{ .reg .u64 t; cvta.to.shared.u64 t, %1; cvt.u32.u64 %0, t; }" : "=r"(a) : "l"(p));
    return a;
}
__device__ __forceinline__ uint32_t swz(uint32_t row, uint32_t segbyte) {
    return row * 128 + (segbyte ^ ((row & 7) << 4));
}
__device__ __forceinline__ void cpasync16(uint32_t dst, const void* src) {
    asm volatile("cp.async.cg.shared.global [%0], [%1], 16;" :: "r"(dst), "l"(src) : "memory");
}
#define CP_COMMIT() asm volatile("cp.async.commit_group;" ::: "memory")
#define CP_WAIT(N)  asm volatile("cp.async.wait_group %0;" :: "n"(N) : "memory")

__device__ __forceinline__ void ldsm4(uint32_t* r, uint32_t addr) {
    asm volatile("ldmatrix.sync.aligned.m8n8.x4.shared.b16 {%0,%1,%2,%3}, [%4];"
        : "=r"(r[0]), "=r"(r[1]), "=r"(r[2]), "=r"(r[3]) : "r"(addr));
}
__device__ __forceinline__ void ldsm2(uint32_t* r, uint32_t addr) {
    asm volatile("ldmatrix.sync.aligned.m8n8.x2.shared.b16 {%0,%1}, [%2];"
        : "=r"(r[0]), "=r"(r[1]) : "r"(addr));
}
__device__ __forceinline__ void mma16816(float* d, const uint32_t* a, const uint32_t* b) {
    asm volatile("mma.sync.aligned.m16n8k16.row.col.f32.f16.f16.f32 "
        "{%0,%1,%2,%3}, {%4,%5,%6,%7}, {%8,%9}, {%0,%1,%2,%3};"
        : "+f"(d[0]), "+f"(d[1]), "+f"(d[2]), "+f"(d[3])
        : "r"(a[0]), "r"(a[1]), "r"(a[2]), "r"(a[3]), "r"(b[0]), "r"(b[1]));
}

__device__ __forceinline__ float sigmoidf_(float x) { return 1.f / (1.f + expf(-x)); }

struct Offs5 { uint32_t a0, a1, b0, b1, b2; };
__device__ __forceinline__ Offs5 make_offs5(int wm, int wn, int lane) {
    Offs5 o;
    const uint32_t sa = (lane >> 4) << 4;
    const uint32_t sb = ((lane >> 3) & 1) << 4;
    o.a0 = swz(wm + (lane & 15), sa);
    o.a1 = swz(wm + 16 + (lane & 15), sa);
    o.b0 = swz(wn + ((lane >> 4) << 3) + (lane & 7), sb);
    o.b1 = swz(wn + 16 + ((lane >> 4) << 3) + (lane & 7), sb);
    o.b2 = swz(wn + 32 + (lane & 7), sb);
    return o;
}
struct Offs6 { uint32_t a0, a1, b0, b1, b2; };
__device__ __forceinline__ Offs6 make_offs6(int wm, int wn, int lane) {
    Offs6 o;
    const uint32_t sa = (lane >> 4) << 4;
    const uint32_t sb = ((lane >> 3) & 1) << 4;
    o.a0 = swz(wm + (lane & 15), sa);
    o.a1 = swz(wm + 16 + (lane & 15), sa);
    o.b0 = swz(wn + ((lane >> 4) << 3) + (lane & 7), sb);
    o.b1 = swz(wn + 16 + ((lane >> 4) << 3) + (lane & 7), sb);
    o.b2 = swz(wn + 32 + ((lane >> 4) << 3) + (lane & 7), sb);
    return o;
}

__device__ __forceinline__ void chunk_mma5(uint32_t abuf, uint32_t bbuf,
                                           const Offs5& o, float acc[2][5][4]) {
#pragma unroll
    for (int k16 = 0; k16 < 4; ++k16) {
        const uint32_t kx = (uint32_t)k16 << 5;
        uint32_t a[2][4], b[5][2], r0[4], r1[4];
        ldsm4(a[0], abuf + (o.a0 ^ kx));
        ldsm4(a[1], abuf + (o.a1 ^ kx));
        ldsm4(r0, bbuf + (o.b0 ^ kx));
        ldsm4(r1, bbuf + (o.b1 ^ kx));
        ldsm2(b[4], bbuf + (o.b2 ^ kx));
        b[0][0] = r0[0]; b[0][1] = r0[1]; b[1][0] = r0[2]; b[1][1] = r0[3];
        b[2][0] = r1[0]; b[2][1] = r1[1]; b[3][0] = r1[2]; b[3][1] = r1[3];
#pragma unroll
        for (int mt = 0; mt < 2; ++mt)
#pragma unroll
            for (int nt = 0; nt < 5; ++nt)
                mma16816(acc[mt][nt], a[mt], b[nt]);
    }
}

__device__ __forceinline__ void chunk_mma6(uint32_t abuf, uint32_t bbuf,
                                           const Offs6& o, float acc[2][6][4]) {
#pragma unroll
    for (int k16 = 0; k16 < 4; ++k16) {
        const uint32_t kx = (uint32_t)k16 << 5;
        uint32_t a[2][4], b[6][2], r0[4], r1[4], r2[4];
        ldsm4(a[0], abuf + (o.a0 ^ kx));
        ldsm4(a[1], abuf + (o.a1 ^ kx));
        ldsm4(r0, bbuf + (o.b0 ^ kx));
        ldsm4(r1, bbuf + (o.b1 ^ kx));
        ldsm4(r2, bbuf + (o.b2 ^ kx));
        b[0][0] = r0[0]; b[0][1] = r0[1]; b[1][0] = r0[2]; b[1][1] = r0[3];
        b[2][0] = r1[0]; b[2][1] = r1[1]; b[3][0] = r1[2]; b[3][1] = r1[3];
        b[4][0] = r2[0]; b[4][1] = r2[1]; b[5][0] = r2[2]; b[5][1] = r2[3];
#pragma unroll
        for (int mt = 0; mt < 2; ++mt)
#pragma unroll
            for (int nt = 0; nt < 6; ++nt)
                mma16816(acc[mt][nt], a[mt], b[nt]);
    }
}

// ---------------- pack kernels ----------------
__global__ void split_emb_kernel(const float* __restrict__ emb) {
    int idx = blockIdx.x * blockDim.x + threadIdx.x;
    if (blockIdx.x == 0 && threadIdx.x < 16) g_sync[threadIdx.x] = 0;   // reset tail barriers
    int stride = gridDim.x * blockDim.x;
    const int total4 = (NN * H) / 4;
    for (int i = idx; i < total4; i += stride) {
        float4 v = reinterpret_cast<const float4*>(emb)[i];
        __half hh[4], hl[4];
        float f[4] = {v.x, v.y, v.z, v.w};
#pragma unroll
        for (int k = 0; k < 4; ++k) {
            hh[k] = __float2half(f[k]);
            hl[k] = __float2half(f[k] - __half2float(hh[k]));
        }
        reinterpret_cast<uint2*>(g_ehi)[i] = *reinterpret_cast<uint2*>(hh);
        reinterpret_cast<uint2*>(g_elo)[i] = *reinterpret_cast<uint2*>(hl);
    }
}

__global__ void pack_w_kernel(
    const float* __restrict__ Wi, const float* __restrict__ bi, const float* __restrict__ Ui,
    const float* __restrict__ Wo, const float* __restrict__ bo, const float* __restrict__ Uo,
    const float* __restrict__ Wu, const float* __restrict__ bu, const float* __restrict__ Uu,
    const float* __restrict__ Wf, const float* __restrict__ bf, const float* __restrict__ Uf)
{
    int idx = blockIdx.x * blockDim.x + threadIdx.x;
    int stride = gridDim.x * blockDim.x;
    if (idx < NCOL) {
        int j = idx / 5, g = idx % 5;
        g_bias[idx] = (g == 0) ? bi[j] : (g == 1) ? bo[j] : (g == 2) ? bu[j] : bf[j];
    }
    for (int e = idx; e < NCOL * KIN; e += stride) {
        int col = e / KIN;
        int k   = e - col * KIN;
        int j = col / 5, g = col % 5;
        float v = 0.f;
        if (k < H) {
            const float* W = (g == 0) ? Wi : (g == 1) ? Wo : (g == 2) ? Wu : Wf;
            v = W[j * H + k];
        } else if (k < 2 * H) {
            int kk = k - H;
            if      (g == 0) v = Ui[j * H + kk];
            else if (g == 1) v = Uo[j * H + kk];
            else if (g == 2) v = Uu[j * H + kk];
            else if (g == 3) v = Uf[j * H + kk];
        } else {
            int kk = k - 2 * H;
            if      (g == 0) v = Ui[H * H + j * H + kk];
            else if (g == 1) v = Uo[H * H + j * H + kk];
            else if (g == 2) v = Uu[H * H + j * H + kk];
            else if (g == 4) v = Uf[H * H + j * H + kk];
        }
        g_B[e] = __float2half(v);
    }
    for (int e = idx; e < NCOL3 * H; e += stride) {
        int col = e / H;
        int k   = e - col * H;
        int j = col / 3, g = col % 3;
        const float* W = (g == 0) ? Wi : (g == 1) ? Wo : Wu;
        g_B3[e] = __float2half(W[j * H + k]);
    }
}

// ---------------- internal level kernel: 128 x 80, KT=64, 2-stage, 3 CTAs/SM ----------------
__global__ void __launch_bounds__(256, 3) hmma_level_kernel(
    int start, int n, float* __restrict__ out)
{
    extern __shared__ char smem[];
    const uint32_t sbase = smem_to_u32(smem);

    const int t    = threadIdx.x;
    const int lane = t & 31;
    const int wid  = t >> 5;
    const int cb   = blockIdx.x;
    const int m0   = blockIdx.y * 128;
    const int gn0  = start + m0;
    const int col0 = cb * 80;

    constexpr int NCH = 24;

    const __half* e_hi = g_ehi + (size_t)gn0 * H;
    const __half* e_lo = g_elo + (size_t)gn0 * H;
    const __half* c1hi = g_hhi + (size_t)(2 * gn0 + 1) * H;
    const __half* c1lo = g_hlo + (size_t)(2 * gn0 + 1) * H;
    const __half* c2hi = g_hhi + (size_t)(2 * gn0 + 2) * H;
    const __half* c2lo = g_hlo + (size_t)(2 * gn0 + 2) * H;

    const int r0 = t >> 3;
    const uint32_t seg8 = (uint32_t)(t & 7) * 8;
    const uint32_t swz0 = swz(r0, (uint32_t)(t & 7) * 16);
    const uint32_t r0H  = (uint32_t)r0 * H;
    const uint32_t r0K  = (uint32_t)r0 * KIN;
    const bool bTail = (t < 128);

    float acc[2][5][4];
#pragma unroll
    for (int mt = 0; mt < 2; ++mt)
#pragma unroll
        for (int nt = 0; nt < 5; ++nt)
#pragma unroll
            for (int r = 0; r < 4; ++r) acc[mt][nt][r] = 0.f;

    auto load_chunk = [&](int c, int st) {
        const int sp  = (c >= 12);
        const int cc  = c - (sp ? 12 : 0);
        const int sec = cc >> 2;
        const uint32_t kof = (uint32_t)(cc & 3) << 6;
        const __half* ab = (sec == 0) ? (sp ? e_lo : e_hi)
                         : (sec == 1) ? (sp ? c1lo : c1hi)
                                      : (sp ? c2lo : c2hi);
        const uint32_t astep = (sec == 0) ? 32u * H : 64u * H;
        const __half* asrc = ab + ((sec == 0) ? r0H : 2 * r0H) + kof + seg8;
        const __half* bsrc = g_B + (size_t)col0 * KIN + cc * 64 + r0K + seg8;
        const uint32_t adst = sbase + st * ASTG + swz0;
        const uint32_t bdst = sbase + OFF_BS_MAIN + st * BSTG + swz0;
        cpasync16(adst +     0, asrc);
        cpasync16(adst +  4096, asrc + astep);
        cpasync16(adst +  8192, asrc + 2 * astep);
        cpasync16(adst + 12288, asrc + 3 * astep);
        cpasync16(bdst +     0, bsrc);
        cpasync16(bdst +  4096, bsrc + 32 * KIN);
        if (bTail) cpasync16(bdst + 8192, bsrc + 64 * KIN);
        CP_COMMIT();
    };

    load_chunk(0, 0);

    const int wm = (wid & 3) * 32;
    const int wn = (wid >> 2) * 40;
    const Offs5 offs = make_offs5(wm, wn, lane);

    for (int c = 0; c < NCH; ++c) {
        const int st = c & 1;
        CP_WAIT(0);
        __syncthreads();
        if (c + 1 < NCH) load_chunk(c + 1, st ^ 1);
        chunk_mma5(sbase + st * ASTG, sbase + OFF_BS_MAIN + st * BSTG, offs, acc);
    }
    __syncthreads();

    float* Cs = reinterpret_cast<float*>(smem);     // [128][84]
#pragma unroll
    for (int mt = 0; mt < 2; ++mt)
#pragma unroll
        for (int nt = 0; nt < 5; ++nt) {
            int m  = wm + mt * 16 + (lane >> 2);
            int nn = wn + nt * 8 + (lane & 3) * 2;
            Cs[m * 84 + nn]           = acc[mt][nt][0];
            Cs[m * 84 + nn + 1]       = acc[mt][nt][1];
            Cs[(m + 8) * 84 + nn]     = acc[mt][nt][2];
            Cs[(m + 8) * 84 + nn + 1] = acc[mt][nt][3];
        }
    __syncthreads();

#pragma unroll
    for (int pass = 0; pass < 8; ++pass) {
        const int task = t + pass * 256;
        const int m = task >> 4;
        const int u = task & 15;
        if (m0 + m >= n) continue;
        const int gn = gn0 + m;
        const int j  = cb * 16 + u;

        const float* cp = &Cs[m * 84 + u * 5];
        float zi = cp[0] + g_bias[j * 5 + 0];
        float zo = cp[1] + g_bias[j * 5 + 1];
        float zu = cp[2] + g_bias[j * 5 + 2];
        float zf0 = cp[3] + g_bias[j * 5 + 3];
        float zf1 = cp[4] + g_bias[j * 5 + 4];
        float vi = sigmoidf_(zi);
        float vo = sigmoidf_(zo);
        float vu = tanhf(zu);
        float cv = vi * vu
                 + sigmoidf_(zf0) * g_c[(size_t)(2 * gn + 1) * H + j]
                 + sigmoidf_(zf1) * g_c[(size_t)(2 * gn + 2) * H + j];
        float h = vo * tanhf(cv);
        __half hh = __float2half(h);
        g_hhi[(size_t)gn * H + j] = hh;
        g_hlo[(size_t)gn * H + j] = __float2half(h - __half2float(hh));
        g_c  [(size_t)gn * H + j] = cv;
        if (out != nullptr && gn == 0) {
            out[j]     = h;
            out[H + j] = cv;
        }
    }
}

// ---------------- leaf kernel: 128 nodes x 96 cols (32 units x 3 gates), K'=512 ----------------
__global__ void __launch_bounds__(256, 3) leaf_kernel(int start, int n)
{
    extern __shared__ char smem[];
    const uint32_t sbase = smem_to_u32(smem);

    const int t    = threadIdx.x;
    const int lane = t & 31;
    const int wid  = t >> 5;
    const int cb   = blockIdx.x;
    const int m0   = blockIdx.y * 128;
    const int gn0  = start + m0;
    const int col0 = cb * 96;

    constexpr int NCH = 8;

    const __half* e_hi = g_ehi + (size_t)gn0 * H;
    const __half* e_lo = g_elo + (size_t)gn0 * H;

    const int r0 = t >> 3;
    const uint32_t seg8 = (uint32_t)(t & 7) * 8;
    const uint32_t swz0 = swz(r0, (uint32_t)(t & 7) * 16);
    const uint32_t r0H  = (uint32_t)r0 * H;

    float acc[2][6][4];
#pragma unroll
    for (int mt = 0; mt < 2; ++mt)
#pragma unroll
        for (int nt = 0; nt < 6; ++nt)
#pragma unroll
            for (int r = 0; r < 4; ++r) acc[mt][nt][r] = 0.f;

    auto load_chunk = [&](int c, int st) {
        const int sp  = (c >= 4);
        const uint32_t kof = (uint32_t)(c & 3) << 6;
        const __half* asrc = (sp ? e_lo : e_hi) + r0H + kof + seg8;
        const __half* bsrc = g_B3 + (size_t)col0 * H + kof + r0H + seg8;
        const uint32_t adst = sbase + st * ASTG + swz0;
        const uint32_t bdst = sbase + OFF_BS_LEAF + st * B3STG + swz0;
        cpasync16(adst +     0, asrc);
        cpasync16(adst +  4096, asrc + 32 * H);
        cpasync16(adst +  8192, asrc + 64 * H);
        cpasync16(adst + 12288, asrc + 96 * H);
        cpasync16(bdst +     0, bsrc);
        cpasync16(bdst +  4096, bsrc + 32 * H);
        cpasync16(bdst +  8192, bsrc + 64 * H);
        CP_COMMIT();
    };

    load_chunk(0, 0);

    const int wm = (wid & 3) * 32;
    const int wn = (wid >> 2) * 48;
    const Offs6 offs = make_offs6(wm, wn, lane);

    for (int c = 0; c < NCH; ++c) {
        const int st = c & 1;
        CP_WAIT(0);
        __syncthreads();
        if (c + 1 < NCH) load_chunk(c + 1, st ^ 1);
        chunk_mma6(sbase + st * ASTG, sbase + OFF_BS_LEAF + st * B3STG, offs, acc);
    }
    __syncthreads();

    float* Cs = reinterpret_cast<float*>(smem);     // [128][100]
#pragma unroll
    for (int mt = 0; mt < 2; ++mt)
#pragma unroll
        for (int nt = 0; nt < 6; ++nt) {
            int m  = wm + mt * 16 + (lane >> 2);
            int nn = wn + nt * 8 + (lane & 3) * 2;
            Cs[m * 100 + nn]           = acc[mt][nt][0];
            Cs[m * 100 + nn + 1]       = acc[mt][nt][1];
            Cs[(m + 8) * 100 + nn]     = acc[mt][nt][2];
            Cs[(m + 8) * 100 + nn + 1] = acc[mt][nt][3];
        }
    __syncthreads();

#pragma unroll
    for (int pass = 0; pass < 16; ++pass) {
        const int task = t + pass * 256;
        const int m = task >> 5;
        const int u = task & 31;
        if (m0 + m >= n) continue;
        const int gn = gn0 + m;
        const int j  = cb * 32 + u;

        const float* cp = &Cs[m * 100 + u * 3];
        float zi = cp[0] + g_bias[j * 5 + 0];
        float zo = cp[1] + g_bias[j * 5 + 1];
        float zu = cp[2] + g_bias[j * 5 + 2];
        float vi = sigmoidf_(zi);
        float vo = sigmoidf_(zo);
        float vu = tanhf(zu);
        float cv = vi * vu;
        float h = vo * tanhf(cv);
        __half hh = __float2half(h);
        g_hhi[(size_t)gn * H + j] = hh;
        g_hlo[(size_t)gn * H + j] = __float2half(h - __half2float(hh));
        g_c  [(size_t)gn * H + j] = cv;
    }
}

// ---------------- fused tail kernel: levels l=LTOP..0, persistent, grid barrier ----------------
// Grid = 128 blocks (<= 148 SMs even at 1 CTA/SM -> co-resident, no deadlock).
#define TAIL_GRID 128
#define LTOP 9

__global__ void __launch_bounds__(256, 2) tail_kernel(float* __restrict__ out)
{
    extern __shared__ char smem[];
    const uint32_t sbase = smem_to_u32(smem);

    const int t    = threadIdx.x;
    const int lane = t & 31;
    const int wid  = t >> 5;

    const int ks = wid >> 1;
    const int wn = (wid & 1) * 40;
    constexpr int PER = 6;

    const Offs5 offs = make_offs5(0, wn, lane);

    for (int l = LTOP; l >= 0; --l) {
        const int n = 1 << l;
        const int start = n - 1;
        const int mtiles = (n + 31) / 32;
        const int tiles = 16 * mtiles;

        for (int tile = blockIdx.x; tile < tiles; tile += TAIL_GRID) {
            const int cb = tile & 15;
            const int my = tile >> 4;
            const int m0 = my * 32;
            const int gn0 = start + m0;
            const int col0 = cb * 80;

            __syncthreads();    // previous tile's Cp reads done before stage reuse

            float acc[2][5][4];
#pragma unroll
            for (int mt = 0; mt < 2; ++mt)
#pragma unroll
                for (int nt = 0; nt < 5; ++nt)
#pragma unroll
                    for (int r = 0; r < 4; ++r) acc[mt][nt][r] = 0.f;

            auto load_step = [&](int step, int st) {
#pragma unroll
                for (int i = 0; i < 14; ++i) {
                    int idx = t + i * 256;
                    int sl  = idx / 896;
                    int rem = idx - sl * 896;
                    int c   = sl * PER + step;
                    int kp  = c * 64;
                    int s   = kp / KIN;
                    int k   = kp - s * KIN;
                    uint32_t sbuf = sbase + (sl * 2 + st) * SLST;
                    if (rem < 256) {
                        int row = rem >> 3, seg = rem & 7;
                        const __half* abase;
                        int astride;
                        if (k < H) {
                            abase = (s == 1 ? g_elo : g_ehi) + (size_t)gn0 * H + k;
                            astride = H;
                        } else if (k < 2 * H) {
                            abase = (s == 1 ? g_hlo : g_hhi) + (size_t)(2 * gn0 + 1) * H + (k - H);
                            astride = 2 * H;
                        } else {
                            abase = (s == 1 ? g_hlo : g_hhi) + (size_t)(2 * gn0 + 2) * H + (k - 2 * H);
                            astride = 2 * H;
                        }
                        cpasync16(sbuf + swz(row, seg * 16),
                                  abase + (size_t)row * astride + seg * 8);
                    } else {
                        int r2 = rem - 256;
                        int row = r2 >> 3, seg = r2 & 7;
                        const __half* bbase = g_B + (size_t)col0 * KIN + k;
                        cpasync16(sbuf + 32 * 128 + swz(row, seg * 16),
                                  bbase + (size_t)row * KIN + seg * 8);
                    }
                }
                CP_COMMIT();
            };

            load_step(0, 0);

            for (int step = 0; step < PER; ++step) {
                const int st = step & 1;
                CP_WAIT(0);
                __syncthreads();
                if (step + 1 < PER) load_step(step + 1, st ^ 1);
                const uint32_t abuf = sbase + (ks * 2 + st) * SLST;
                chunk_mma5(abuf, abuf + 32 * 128, offs, acc);
            }
            __syncthreads();

            float* Cp = reinterpret_cast<float*>(smem);   // [4][32][84]
#pragma unroll
            for (int mt = 0; mt < 2; ++mt)
#pragma unroll
                for (int nt = 0; nt < 5; ++nt) {
                    int m  = mt * 16 + (lane >> 2);
                    int nn = wn + nt * 8 + (lane & 3) * 2;
                    float* dst = Cp + ks * (32 * 84);
                    dst[m * 84 + nn]           = acc[mt][nt][0];
                    dst[m * 84 + nn + 1]       = acc[mt][nt][1];
                    dst[(m + 8) * 84 + nn]     = acc[mt][nt][2];
                    dst[(m + 8) * 84 + nn + 1] = acc[mt][nt][3];
                }
            __syncthreads();

#pragma unroll
            for (int pass = 0; pass < 2; ++pass) {
                const int task = t + pass * 256;
                const int m = task >> 4;
                const int u = task & 15;
                if (m0 + m >= n) continue;
                const int gn = gn0 + m;
                const int j  = cb * 16 + u;

                float z[5];
#pragma unroll
                for (int g = 0; g < 5; ++g) {
                    float s = g_bias[j * 5 + g];
#pragma unroll
                    for (int sl = 0; sl < 4; ++sl)
                        s += Cp[sl * (32 * 84) + m * 84 + u * 5 + g];
                    z[g] = s;
                }
                float vi = sigmoidf_(z[0]);
                float vo = sigmoidf_(z[1]);
                float vu = tanhf(z[2]);
                float cv = vi * vu
                         + sigmoidf_(z[3]) * g_c[(size_t)(2 * gn + 1) * H + j]
                         + sigmoidf_(z[4]) * g_c[(size_t)(2 * gn + 2) * H + j];
                float h = vo * tanhf(cv);
                __half hh = __float2half(h);
                g_hhi[(size_t)gn * H + j] = hh;
                g_hlo[(size_t)gn * H + j] = __float2half(h - __half2float(hh));
                g_c  [(size_t)gn * H + j] = cv;
                if (l == 0 && gn == 0) {
                    out[j]     = h;
                    out[H + j] = cv;
                }
            }
        }

        // ---- grid barrier between levels ----
        if (l > 0) {
            __syncthreads();
            if (t == 0) {
                __threadfence();
                atomicAdd(&g_sync[l], 1u);
                while (atomicAdd(&g_sync[l], 0u) < (unsigned)TAIL_GRID) { }
            }
            __syncthreads();
        }
    }
}

// ---------------- host launcher ----------------
extern "C" void kernel_launch(void* const* d_in, const int* in_sizes, int n_in,
                              void* d_out, int out_size)
{
    const float* emb = (const float*)d_in[0];
    const float* Wi  = (const float*)d_in[1];
    const float* bi  = (const float*)d_in[2];
    const float* Ui  = (const float*)d_in[3];
    const float* Wo  = (const float*)d_in[4];
    const float* bo  = (const float*)d_in[5];
    const float* Uo  = (const float*)d_in[6];
    const float* Wu  = (const float*)d_in[7];
    const float* bu  = (const float*)d_in[8];
    const float* Uu  = (const float*)d_in[9];
    const float* Wf  = (const float*)d_in[10];
    const float* bf  = (const float*)d_in[11];
    const float* Uf  = (const float*)d_in[12];

    cudaFuncSetAttribute(hmma_level_kernel, cudaFuncAttributeMaxDynamicSharedMemorySize, SMEM_MAIN);
    cudaFuncSetAttribute(leaf_kernel,       cudaFuncAttributeMaxDynamicSharedMemorySize, SMEM_LEAF);
    cudaFuncSetAttribute(tail_kernel,       cudaFuncAttributeMaxDynamicSharedMemorySize, SMEM_SMALL);

    split_emb_kernel<<<2048, 256>>>(emb);
    pack_w_kernel<<<1024, 256>>>(Wi, bi, Ui, Wo, bo, Uo, Wu, bu, Uu, Wf, bf, Uf);

    // leaves: level 15, n = 32768, 3 gates only
    {
        int n = 1 << (DEPTH - 1);
        int start = n - 1;
        dim3 grid(8, n / 128);
        leaf_kernel<<<grid, 256, SMEM_LEAF>>>(start, n);
    }
    // big internal levels (n >= 1024)
    for (int l = DEPTH - 2; l > LTOP; --l) {
        int n = 1 << l;
        int start = n - 1;
        dim3 grid(16, n / 128);
        hmma_level_kernel<<<grid, 256, SMEM_MAIN>>>(start, n, nullptr);
    }
    // fused tail: levels LTOP..0 in one persistent launch
    tail_kernel<<<TAIL_GRID, 256, SMEM_SMALL>>>((float*)d_out);
}

// round 16
// speedup vs baseline: 1.2746x; 1.2574x over previous
#include <cuda_runtime.h>
#include <cuda_fp16.h>
#include <cstdint>
#include <math.h>

#define DEPTH 16
#define NN    65535
#define H     256
#define KIN   768
#define NCOL  1280           // 5 gates * 256 units, col = j*5+g (internal)
#define NCOL3 768            // 3 gates * 256 units, col = j*3+g (leaves)

// ---------------- device scratch (no cudaMalloc allowed) ----------------
__device__ __half g_ehi[(size_t)NN * H];
__device__ __half g_elo[(size_t)NN * H];
__device__ __half g_h  [(size_t)NN * H];       // h, fp16 (no lo term)
__device__ float  g_c  [(size_t)NN * H];
__device__ __half g_B  [(size_t)NCOL * KIN];   // [col][k], internal
__device__ __half g_B3 [(size_t)NCOL3 * H];    // [col][k], leaves (x-part only)
__device__ float  g_bias[NCOL];

// ---------------- smem layouts (SW128 swizzled, 128B rows) ----------------
static constexpr int ASTG = 128 * 128;                     // 16384
static constexpr int BSTG = 80 * 128;                      // 10240
static constexpr int OFF_BS_MAIN = 2 * ASTG;               // 32768
static constexpr int SMEM_MAIN   = 2 * (ASTG + BSTG);      // 53248 (x3 CTAs)
static constexpr int B3STG = 96 * 128;                     // 12288
static constexpr int OFF_BS_LEAF = 2 * ASTG;               // 32768
static constexpr int SMEM_LEAF   = 2 * (ASTG + B3STG);     // 57344 (x3 CTAs)
static constexpr int SLST = 32 * 128 + 80 * 128;           // 14336
static constexpr int SMEM_SMALL = 8 * SLST;                // 114688 (2 CTAs/SM)

// ---------------- PTX helpers (baseline sm_80+) ----------------
__device__ __forceinline__ uint32_t smem_to_u32(const void* p) {
    uint32_t a;
    asm("{ .reg .u64 t; cvta.to.shared.u64 t, %1; cvt.u32.u64 %0, t; }" : "=r"(a) : "l"(p));
    return a;
}
__device__ __forceinline__ uint32_t swz(uint32_t row, uint32_t segbyte) {
    return row * 128 + (segbyte ^ ((row & 7) << 4));
}
__device__ __forceinline__ void cpasync16(uint32_t dst, const void* src) {
    asm volatile("cp.async.cg.shared.global [%0], [%1], 16;" :: "r"(dst), "l"(src) : "memory");
}
#define CP_COMMIT() asm volatile("cp.async.commit_group;" ::: "memory")
#define CP_WAIT(N)  asm volatile("cp.async.wait_group %0;" :: "n"(N) : "memory")

__device__ __forceinline__ void ldsm4(uint32_t* r, uint32_t addr) {
    asm volatile("ldmatrix.sync.aligned.m8n8.x4.shared.b16 {%0,%1,%2,%3}, [%4];"
        : "=r"(r[0]), "=r"(r[1]), "=r"(r[2]), "=r"(r[3]) : "r"(addr));
}
__device__ __forceinline__ void ldsm2(uint32_t* r, uint32_t addr) {
    asm volatile("ldmatrix.sync.aligned.m8n8.x2.shared.b16 {%0,%1}, [%2];"
        : "=r"(r[0]), "=r"(r[1]) : "r"(addr));
}
__device__ __forceinline__ void mma16816(float* d, const uint32_t* a, const uint32_t* b) {
    asm volatile("mma.sync.aligned.m16n8k16.row.col.f32.f16.f16.f32 "
        "{%0,%1,%2,%3}, {%4,%5,%6,%7}, {%8,%9}, {%0,%1,%2,%3};"
        : "+f"(d[0]), "+f"(d[1]), "+f"(d[2]), "+f"(d[3])
        : "r"(a[0]), "r"(a[1]), "r"(a[2]), "r"(a[3]), "r"(b[0]), "r"(b[1]));
}

__device__ __forceinline__ float sigmoidf_(float x) { return 1.f / (1.f + expf(-x)); }

struct Offs5 { uint32_t a0, a1, b0, b1, b2; };
__device__ __forceinline__ Offs5 make_offs5(int wm, int wn, int lane) {
    Offs5 o;
    const uint32_t sa = (lane >> 4) << 4;
    const uint32_t sb = ((lane >> 3) & 1) << 4;
    o.a0 = swz(wm + (lane & 15), sa);
    o.a1 = swz(wm + 16 + (lane & 15), sa);
    o.b0 = swz(wn + ((lane >> 4) << 3) + (lane & 7), sb);
    o.b1 = swz(wn + 16 + ((lane >> 4) << 3) + (lane & 7), sb);
    o.b2 = swz(wn + 32 + (lane & 7), sb);
    return o;
}
struct Offs6 { uint32_t a0, a1, b0, b1, b2; };
__device__ __forceinline__ Offs6 make_offs6(int wm, int wn, int lane) {
    Offs6 o;
    const uint32_t sa = (lane >> 4) << 4;
    const uint32_t sb = ((lane >> 3) & 1) << 4;
    o.a0 = swz(wm + (lane & 15), sa);
    o.a1 = swz(wm + 16 + (lane & 15), sa);
    o.b0 = swz(wn + ((lane >> 4) << 3) + (lane & 7), sb);
    o.b1 = swz(wn + 16 + ((lane >> 4) << 3) + (lane & 7), sb);
    o.b2 = swz(wn + 32 + ((lane >> 4) << 3) + (lane & 7), sb);
    return o;
}

__device__ __forceinline__ void chunk_mma5(uint32_t abuf, uint32_t bbuf,
                                           const Offs5& o, float acc[2][5][4]) {
#pragma unroll
    for (int k16 = 0; k16 < 4; ++k16) {
        const uint32_t kx = (uint32_t)k16 << 5;
        uint32_t a[2][4], b[5][2], r0[4], r1[4];
        ldsm4(a[0], abuf + (o.a0 ^ kx));
        ldsm4(a[1], abuf + (o.a1 ^ kx));
        ldsm4(r0, bbuf + (o.b0 ^ kx));
        ldsm4(r1, bbuf + (o.b1 ^ kx));
        ldsm2(b[4], bbuf + (o.b2 ^ kx));
        b[0][0] = r0[0]; b[0][1] = r0[1]; b[1][0] = r0[2]; b[1][1] = r0[3];
        b[2][0] = r1[0]; b[2][1] = r1[1]; b[3][0] = r1[2]; b[3][1] = r1[3];
#pragma unroll
        for (int mt = 0; mt < 2; ++mt)
#pragma unroll
            for (int nt = 0; nt < 5; ++nt)
                mma16816(acc[mt][nt], a[mt], b[nt]);
    }
}

__device__ __forceinline__ void chunk_mma6(uint32_t abuf, uint32_t bbuf,
                                           const Offs6& o, float acc[2][6][4]) {
#pragma unroll
    for (int k16 = 0; k16 < 4; ++k16) {
        const uint32_t kx = (uint32_t)k16 << 5;
        uint32_t a[2][4], b[6][2], r0[4], r1[4], r2[4];
        ldsm4(a[0], abuf + (o.a0 ^ kx));
        ldsm4(a[1], abuf + (o.a1 ^ kx));
        ldsm4(r0, bbuf + (o.b0 ^ kx));
        ldsm4(r1, bbuf + (o.b1 ^ kx));
        ldsm4(r2, bbuf + (o.b2 ^ kx));
        b[0][0] = r0[0]; b[0][1] = r0[1]; b[1][0] = r0[2]; b[1][1] = r0[3];
        b[2][0] = r1[0]; b[2][1] = r1[1]; b[3][0] = r1[2]; b[3][1] = r1[3];
        b[4][0] = r2[0]; b[4][1] = r2[1]; b[5][0] = r2[2]; b[5][1] = r2[3];
#pragma unroll
        for (int mt = 0; mt < 2; ++mt)
#pragma unroll
            for (int nt = 0; nt < 6; ++nt)
                mma16816(acc[mt][nt], a[mt], b[nt]);
    }
}

// ---------------- pack kernels ----------------
__global__ void split_emb_kernel(const float* __restrict__ emb) {
    int idx = blockIdx.x * blockDim.x + threadIdx.x;
    int stride = gridDim.x * blockDim.x;
    const int total4 = (NN * H) / 4;
    for (int i = idx; i < total4; i += stride) {
        float4 v = reinterpret_cast<const float4*>(emb)[i];
        __half hh[4], hl[4];
        float f[4] = {v.x, v.y, v.z, v.w};
#pragma unroll
        for (int k = 0; k < 4; ++k) {
            hh[k] = __float2half(f[k]);
            hl[k] = __float2half(f[k] - __half2float(hh[k]));
        }
        reinterpret_cast<uint2*>(g_ehi)[i] = *reinterpret_cast<uint2*>(hh);
        reinterpret_cast<uint2*>(g_elo)[i] = *reinterpret_cast<uint2*>(hl);
    }
}

__global__ void pack_w_kernel(
    const float* __restrict__ Wi, const float* __restrict__ bi, const float* __restrict__ Ui,
    const float* __restrict__ Wo, const float* __restrict__ bo, const float* __restrict__ Uo,
    const float* __restrict__ Wu, const float* __restrict__ bu, const float* __restrict__ Uu,
    const float* __restrict__ Wf, const float* __restrict__ bf, const float* __restrict__ Uf)
{
    int idx = blockIdx.x * blockDim.x + threadIdx.x;
    int stride = gridDim.x * blockDim.x;
    if (idx < NCOL) {
        int j = idx / 5, g = idx % 5;
        g_bias[idx] = (g == 0) ? bi[j] : (g == 1) ? bo[j] : (g == 2) ? bu[j] : bf[j];
    }
    for (int e = idx; e < NCOL * KIN; e += stride) {
        int col = e / KIN;
        int k   = e - col * KIN;
        int j = col / 5, g = col % 5;
        float v = 0.f;
        if (k < H) {
            const float* W = (g == 0) ? Wi : (g == 1) ? Wo : (g == 2) ? Wu : Wf;
            v = W[j * H + k];
        } else if (k < 2 * H) {
            int kk = k - H;
            if      (g == 0) v = Ui[j * H + kk];
            else if (g == 1) v = Uo[j * H + kk];
            else if (g == 2) v = Uu[j * H + kk];
            else if (g == 3) v = Uf[j * H + kk];
        } else {
            int kk = k - 2 * H;
            if      (g == 0) v = Ui[H * H + j * H + kk];
            else if (g == 1) v = Uo[H * H + j * H + kk];
            else if (g == 2) v = Uu[H * H + j * H + kk];
            else if (g == 4) v = Uf[H * H + j * H + kk];
        }
        g_B[e] = __float2half(v);
    }
    for (int e = idx; e < NCOL3 * H; e += stride) {
        int col = e / H;
        int k   = e - col * H;
        int j = col / 3, g = col % 3;
        const float* W = (g == 0) ? Wi : (g == 1) ? Wo : Wu;
        g_B3[e] = __float2half(W[j * H + k]);
    }
}

// ---------------- internal level kernel: 128 x 80, KT=64, 2-stage, 3 CTAs/SM ----------------
// Extended K' = 16 chunks: c 0..11 = hi of [emb|c1h|c2h], c 12..15 = emb_lo.
__global__ void __launch_bounds__(256, 3) hmma_level_kernel(
    int start, int n, float* __restrict__ out)
{
    extern __shared__ char smem[];
    const uint32_t sbase = smem_to_u32(smem);

    const int t    = threadIdx.x;
    const int lane = t & 31;
    const int wid  = t >> 5;
    const int cb   = blockIdx.x;
    const int m0   = blockIdx.y * 128;
    const int gn0  = start + m0;
    const int col0 = cb * 80;

    constexpr int NCH = 16;

    const __half* e_hi = g_ehi + (size_t)gn0 * H;
    const __half* e_lo = g_elo + (size_t)gn0 * H;
    const __half* c1h  = g_h + (size_t)(2 * gn0 + 1) * H;
    const __half* c2h  = g_h + (size_t)(2 * gn0 + 2) * H;

    const int r0 = t >> 3;
    const uint32_t seg8 = (uint32_t)(t & 7) * 8;
    const uint32_t swz0 = swz(r0, (uint32_t)(t & 7) * 16);
    const uint32_t r0H  = (uint32_t)r0 * H;
    const uint32_t r0K  = (uint32_t)r0 * KIN;
    const bool bTail = (t < 128);

    float acc[2][5][4];
#pragma unroll
    for (int mt = 0; mt < 2; ++mt)
#pragma unroll
        for (int nt = 0; nt < 5; ++nt)
#pragma unroll
            for (int r = 0; r < 4; ++r) acc[mt][nt][r] = 0.f;

    auto load_chunk = [&](int c, int st) {
        const bool lo = (c >= 12);
        const int cc  = lo ? (c - 12) : c;
        const int sec = lo ? 0 : (cc >> 2);
        const int kk4 = lo ? cc : (cc & 3);
        const uint32_t kof = (uint32_t)kk4 << 6;
        const __half* ab = lo ? e_lo
                         : (sec == 0) ? e_hi
                         : (sec == 1) ? c1h : c2h;
        const uint32_t astep = (sec == 0) ? 32u * H : 64u * H;
        const __half* asrc = ab + ((sec == 0) ? r0H : 2 * r0H) + kof + seg8;
        const int bk = (lo ? kk4 : cc) * 64;
        const __half* bsrc = g_B + (size_t)col0 * KIN + bk + r0K + seg8;
        const uint32_t adst = sbase + st * ASTG + swz0;
        const uint32_t bdst = sbase + OFF_BS_MAIN + st * BSTG + swz0;
        cpasync16(adst +     0, asrc);
        cpasync16(adst +  4096, asrc + astep);
        cpasync16(adst +  8192, asrc + 2 * astep);
        cpasync16(adst + 12288, asrc + 3 * astep);
        cpasync16(bdst +     0, bsrc);
        cpasync16(bdst +  4096, bsrc + 32 * KIN);
        if (bTail) cpasync16(bdst + 8192, bsrc + 64 * KIN);
        CP_COMMIT();
    };

    load_chunk(0, 0);

    const int wm = (wid & 3) * 32;
    const int wn = (wid >> 2) * 40;
    const Offs5 offs = make_offs5(wm, wn, lane);

    for (int c = 0; c < NCH; ++c) {
        const int st = c & 1;
        CP_WAIT(0);
        __syncthreads();
        if (c + 1 < NCH) load_chunk(c + 1, st ^ 1);
        chunk_mma5(sbase + st * ASTG, sbase + OFF_BS_MAIN + st * BSTG, offs, acc);
    }
    __syncthreads();

    float* Cs = reinterpret_cast<float*>(smem);     // [128][84]
#pragma unroll
    for (int mt = 0; mt < 2; ++mt)
#pragma unroll
        for (int nt = 0; nt < 5; ++nt) {
            int m  = wm + mt * 16 + (lane >> 2);
            int nn = wn + nt * 8 + (lane & 3) * 2;
            Cs[m * 84 + nn]           = acc[mt][nt][0];
            Cs[m * 84 + nn + 1]       = acc[mt][nt][1];
            Cs[(m + 8) * 84 + nn]     = acc[mt][nt][2];
            Cs[(m + 8) * 84 + nn + 1] = acc[mt][nt][3];
        }
    __syncthreads();

#pragma unroll
    for (int pass = 0; pass < 8; ++pass) {
        const int task = t + pass * 256;
        const int m = task >> 4;
        const int u = task & 15;
        if (m0 + m >= n) continue;
        const int gn = gn0 + m;
        const int j  = cb * 16 + u;

        const float* cp = &Cs[m * 84 + u * 5];
        float zi = cp[0] + g_bias[j * 5 + 0];
        float zo = cp[1] + g_bias[j * 5 + 1];
        float zu = cp[2] + g_bias[j * 5 + 2];
        float zf0 = cp[3] + g_bias[j * 5 + 3];
        float zf1 = cp[4] + g_bias[j * 5 + 4];
        float vi = sigmoidf_(zi);
        float vo = sigmoidf_(zo);
        float vu = tanhf(zu);
        float cv = vi * vu
                 + sigmoidf_(zf0) * g_c[(size_t)(2 * gn + 1) * H + j]
                 + sigmoidf_(zf1) * g_c[(size_t)(2 * gn + 2) * H + j];
        float h = vo * tanhf(cv);
        g_h[(size_t)gn * H + j] = __float2half(h);
        g_c[(size_t)gn * H + j] = cv;
        if (out != nullptr && gn == 0) {
            out[j]     = h;
            out[H + j] = cv;
        }
    }
}

// ---------------- leaf kernel: 128 nodes x 96 cols (32 units x 3 gates), K'=512 ----------------
__global__ void __launch_bounds__(256, 3) leaf_kernel(int start, int n)
{
    extern __shared__ char smem[];
    const uint32_t sbase = smem_to_u32(smem);

    const int t    = threadIdx.x;
    const int lane = t & 31;
    const int wid  = t >> 5;
    const int cb   = blockIdx.x;
    const int m0   = blockIdx.y * 128;
    const int gn0  = start + m0;
    const int col0 = cb * 96;

    constexpr int NCH = 8;

    const __half* e_hi = g_ehi + (size_t)gn0 * H;
    const __half* e_lo = g_elo + (size_t)gn0 * H;

    const int r0 = t >> 3;
    const uint32_t seg8 = (uint32_t)(t & 7) * 8;
    const uint32_t swz0 = swz(r0, (uint32_t)(t & 7) * 16);
    const uint32_t r0H  = (uint32_t)r0 * H;

    float acc[2][6][4];
#pragma unroll
    for (int mt = 0; mt < 2; ++mt)
#pragma unroll
        for (int nt = 0; nt < 6; ++nt)
#pragma unroll
            for (int r = 0; r < 4; ++r) acc[mt][nt][r] = 0.f;

    auto load_chunk = [&](int c, int st) {
        const int sp  = (c >= 4);
        const uint32_t kof = (uint32_t)(c & 3) << 6;
        const __half* asrc = (sp ? e_lo : e_hi) + r0H + kof + seg8;
        const __half* bsrc = g_B3 + (size_t)col0 * H + kof + r0H + seg8;
        const uint32_t adst = sbase + st * ASTG + swz0;
        const uint32_t bdst = sbase + OFF_BS_LEAF + st * B3STG + swz0;
        cpasync16(adst +     0, asrc);
        cpasync16(adst +  4096, asrc + 32 * H);
        cpasync16(adst +  8192, asrc + 64 * H);
        cpasync16(adst + 12288, asrc + 96 * H);
        cpasync16(bdst +     0, bsrc);
        cpasync16(bdst +  4096, bsrc + 32 * H);
        cpasync16(bdst +  8192, bsrc + 64 * H);
        CP_COMMIT();
    };

    load_chunk(0, 0);

    const int wm = (wid & 3) * 32;
    const int wn = (wid >> 2) * 48;
    const Offs6 offs = make_offs6(wm, wn, lane);

    for (int c = 0; c < NCH; ++c) {
        const int st = c & 1;
        CP_WAIT(0);
        __syncthreads();
        if (c + 1 < NCH) load_chunk(c + 1, st ^ 1);
        chunk_mma6(sbase + st * ASTG, sbase + OFF_BS_LEAF + st * B3STG, offs, acc);
    }
    __syncthreads();

    float* Cs = reinterpret_cast<float*>(smem);     // [128][100]
#pragma unroll
    for (int mt = 0; mt < 2; ++mt)
#pragma unroll
        for (int nt = 0; nt < 6; ++nt) {
            int m  = wm + mt * 16 + (lane >> 2);
            int nn = wn + nt * 8 + (lane & 3) * 2;
            Cs[m * 100 + nn]           = acc[mt][nt][0];
            Cs[m * 100 + nn + 1]       = acc[mt][nt][1];
            Cs[(m + 8) * 100 + nn]     = acc[mt][nt][2];
            Cs[(m + 8) * 100 + nn + 1] = acc[mt][nt][3];
        }
    __syncthreads();

#pragma unroll
    for (int pass = 0; pass < 16; ++pass) {
        const int task = t + pass * 256;
        const int m = task >> 5;
        const int u = task & 31;
        if (m0 + m >= n) continue;
        const int gn = gn0 + m;
        const int j  = cb * 32 + u;

        const float* cp = &Cs[m * 100 + u * 3];
        float zi = cp[0] + g_bias[j * 5 + 0];
        float zo = cp[1] + g_bias[j * 5 + 1];
        float zu = cp[2] + g_bias[j * 5 + 2];
        float vi = sigmoidf_(zi);
        float vo = sigmoidf_(zo);
        float vu = tanhf(zu);
        float cv = vi * vu;
        float h = vo * tanhf(cv);
        g_h[(size_t)gn * H + j] = __float2half(h);
        g_c[(size_t)gn * H + j] = cv;
    }
}

// ---------------- small-level kernel: split-K across warps, M tile = 32, 2 CTAs/SM ----------------
// 16 chunks / 4 K-slices = 4 per slice: slice0 emb_hi, slice1 c1h, slice2 c2h, slice3 emb_lo.
__global__ void __launch_bounds__(256, 2) smallk_kernel(int start, int n, float* __restrict__ out)
{
    extern __shared__ char smem[];
    const uint32_t sbase = smem_to_u32(smem);

    const int t    = threadIdx.x;
    const int lane = t & 31;
    const int wid  = t >> 5;
    const int cb   = blockIdx.x;
    const int m0   = blockIdx.y * 32;
    const int gn0  = start + m0;
    const int col0 = cb * 80;

    const int ks = wid >> 1;
    const int wn = (wid & 1) * 40;

    constexpr int PER = 4;                // chunks per slice (16/4)

    float acc[2][5][4];
#pragma unroll
    for (int mt = 0; mt < 2; ++mt)
#pragma unroll
        for (int nt = 0; nt < 5; ++nt)
#pragma unroll
            for (int r = 0; r < 4; ++r) acc[mt][nt][r] = 0.f;

    auto load_step = [&](int step, int st) {
#pragma unroll
        for (int i = 0; i < 14; ++i) {
            int idx = t + i * 256;
            int sl  = idx / 896;
            int rem = idx - sl * 896;
            int c   = sl * PER + step;      // 0..15
            uint32_t sbuf = sbase + (sl * 2 + st) * SLST;
            // chunk -> A section & k offset
            const __half* abase;
            int astride;
            int bk;
            if (c < 4) {
                abase = g_ehi + (size_t)gn0 * H + c * 64;          astride = H;     bk = c * 64;
            } else if (c < 8) {
                abase = g_h + (size_t)(2 * gn0 + 1) * H + (c - 4) * 64; astride = 2 * H; bk = 256 + (c - 4) * 64;
            } else if (c < 12) {
                abase = g_h + (size_t)(2 * gn0 + 2) * H + (c - 8) * 64; astride = 2 * H; bk = 512 + (c - 8) * 64;
            } else {
                abase = g_elo + (size_t)gn0 * H + (c - 12) * 64;   astride = H;     bk = (c - 12) * 64;
            }
            if (rem < 256) {
                int row = rem >> 3, seg = rem & 7;
                cpasync16(sbuf + swz(row, seg * 16),
                          abase + (size_t)row * astride + seg * 8);
            } else {
                int r2 = rem - 256;
                int row = r2 >> 3, seg = r2 & 7;
                const __half* bbase = g_B + (size_t)col0 * KIN + bk;
                cpasync16(sbuf + 32 * 128 + swz(row, seg * 16),
                          bbase + (size_t)row * KIN + seg * 8);
            }
        }
        CP_COMMIT();
    };

    load_step(0, 0);

    const Offs5 offs = make_offs5(0, wn, lane);

    for (int step = 0; step < PER; ++step) {
        const int st = step & 1;
        CP_WAIT(0);
        __syncthreads();
        if (step + 1 < PER) load_step(step + 1, st ^ 1);
        const uint32_t abuf = sbase + (ks * 2 + st) * SLST;
        chunk_mma5(abuf, abuf + 32 * 128, offs, acc);
    }
    __syncthreads();

    float* Cp = reinterpret_cast<float*>(smem);   // [4][32][84]
#pragma unroll
    for (int mt = 0; mt < 2; ++mt)
#pragma unroll
        for (int nt = 0; nt < 5; ++nt) {
            int m  = mt * 16 + (lane >> 2);
            int nn = wn + nt * 8 + (lane & 3) * 2;
            float* dst = Cp + ks * (32 * 84);
            dst[m * 84 + nn]           = acc[mt][nt][0];
            dst[m * 84 + nn + 1]       = acc[mt][nt][1];
            dst[(m + 8) * 84 + nn]     = acc[mt][nt][2];
            dst[(m + 8) * 84 + nn + 1] = acc[mt][nt][3];
        }
    __syncthreads();

#pragma unroll
    for (int pass = 0; pass < 2; ++pass) {
        const int task = t + pass * 256;
        const int m = task >> 4;
        const int u = task & 15;
        if (m0 + m >= n) continue;
        const int gn = gn0 + m;
        const int j  = cb * 16 + u;

        float z[5];
#pragma unroll
        for (int g = 0; g < 5; ++g) {
            float s = g_bias[j * 5 + g];
#pragma unroll
            for (int sl = 0; sl < 4; ++sl)
                s += Cp[sl * (32 * 84) + m * 84 + u * 5 + g];
            z[g] = s;
        }
        float vi = sigmoidf_(z[0]);
        float vo = sigmoidf_(z[1]);
        float vu = tanhf(z[2]);
        float cv = vi * vu
                 + sigmoidf_(z[3]) * g_c[(size_t)(2 * gn + 1) * H + j]
                 + sigmoidf_(z[4]) * g_c[(size_t)(2 * gn + 2) * H + j];
        float h = vo * tanhf(cv);
        g_h[(size_t)gn * H + j] = __float2half(h);
        g_c[(size_t)gn * H + j] = cv;
        if (out != nullptr && gn == 0) {
            out[j]     = h;
            out[H + j] = cv;
        }
    }
}

// ---------------- host launcher ----------------
extern "C" void kernel_launch(void* const* d_in, const int* in_sizes, int n_in,
                              void* d_out, int out_size)
{
    const float* emb = (const float*)d_in[0];
    const float* Wi  = (const float*)d_in[1];
    const float* bi  = (const float*)d_in[2];
    const float* Ui  = (const float*)d_in[3];
    const float* Wo  = (const float*)d_in[4];
    const float* bo  = (const float*)d_in[5];
    const float* Uo  = (const float*)d_in[6];
    const float* Wu  = (const float*)d_in[7];
    const float* bu  = (const float*)d_in[8];
    const float* Uu  = (const float*)d_in[9];
    const float* Wf  = (const float*)d_in[10];
    const float* bf  = (const float*)d_in[11];
    const float* Uf  = (const float*)d_in[12];

    cudaFuncSetAttribute(hmma_level_kernel, cudaFuncAttributeMaxDynamicSharedMemorySize, SMEM_MAIN);
    cudaFuncSetAttribute(leaf_kernel,       cudaFuncAttributeMaxDynamicSharedMemorySize, SMEM_LEAF);
    cudaFuncSetAttribute(smallk_kernel,     cudaFuncAttributeMaxDynamicSharedMemorySize, SMEM_SMALL);

    split_emb_kernel<<<2048, 256>>>(emb);
    pack_w_kernel<<<1024, 256>>>(Wi, bi, Ui, Wo, bo, Uo, Wu, bu, Uu, Wf, bf, Uf);

    // leaves: level 15, n = 32768, 3 gates only (emb hi+lo)
    {
        int n = 1 << (DEPTH - 1);
        int start = n - 1;
        dim3 grid(8, n / 128);
        leaf_kernel<<<grid, 256, SMEM_LEAF>>>(start, n);
    }
    // internal levels bottom-up
    for (int l = DEPTH - 2; l >= 0; --l) {
        int n = 1 << l;
        int start = n - 1;
        float* outp = (l == 0) ? (float*)d_out : nullptr;
        if (n >= 1024) {
            dim3 grid(16, n / 128);
            hmma_level_kernel<<<grid, 256, SMEM_MAIN>>>(start, n, outp);
        } else {
            dim3 grid(16, (n + 31) / 32);
            smallk_kernel<<<grid, 256, SMEM_SMALL>>>(start, n, outp);
        }
    }
}

// round 17
// speedup vs baseline: 1.4999x; 1.1768x over previous
#include <cuda_runtime.h>
#include <cuda_fp16.h>
#include <cstdint>
#include <math.h>

#define DEPTH 16
#define NN    65535
#define H     256
#define KIN   768
#define NCOL  1280           // 5 gates * 256 units, col = j*5+g (internal)
#define NCOL3 768            // 3 gates * 256 units, col = j*3+g (leaves)

// ---------------- device scratch (no cudaMalloc allowed) ----------------
__device__ __half g_e  [(size_t)NN * H];       // emb, fp16
__device__ __half g_h  [(size_t)NN * H];       // h, fp16
__device__ float  g_c  [(size_t)NN * H];
__device__ __half g_B  [(size_t)NCOL * KIN];   // [col][k], internal
__device__ __half g_B3 [(size_t)NCOL3 * H];    // [col][k], leaves (x-part only)
__device__ float  g_bias[NCOL];

// ---------------- smem layouts (SW128 swizzled, 128B rows) ----------------
static constexpr int ASTG = 128 * 128;                     // 16384
static constexpr int BSTG = 80 * 128;                      // 10240
static constexpr int OFF_BS_MAIN = 2 * ASTG;               // 32768
static constexpr int SMEM_MAIN   = 2 * (ASTG + BSTG);      // 53248 (x3 CTAs)
static constexpr int B3STG = 96 * 128;                     // 12288
static constexpr int OFF_BS_LEAF = 2 * ASTG;               // 32768
static constexpr int SMEM_LEAF   = 2 * (ASTG + B3STG);     // 57344 (x3 CTAs)
static constexpr int SLST = 32 * 128 + 80 * 128;           // 14336
static constexpr int SMEM_SMALL = 8 * SLST;                // 114688 (2 CTAs/SM)

// ---------------- PTX helpers (baseline sm_80+) ----------------
__device__ __forceinline__ uint32_t smem_to_u32(const void* p) {
    uint32_t a;
    asm("{ .reg .u64 t; cvta.to.shared.u64 t, %1; cvt.u32.u64 %0, t; }" : "=r"(a) : "l"(p));
    return a;
}
__device__ __forceinline__ uint32_t swz(uint32_t row, uint32_t segbyte) {
    return row * 128 + (segbyte ^ ((row & 7) << 4));
}
__device__ __forceinline__ void cpasync16(uint32_t dst, const void* src) {
    asm volatile("cp.async.cg.shared.global [%0], [%1], 16;" :: "r"(dst), "l"(src) : "memory");
}
#define CP_COMMIT() asm volatile("cp.async.commit_group;" ::: "memory")
#define CP_WAIT(N)  asm volatile("cp.async.wait_group %0;" :: "n"(N) : "memory")

__device__ __forceinline__ void ldsm4(uint32_t* r, uint32_t addr) {
    asm volatile("ldmatrix.sync.aligned.m8n8.x4.shared.b16 {%0,%1,%2,%3}, [%4];"
        : "=r"(r[0]), "=r"(r[1]), "=r"(r[2]), "=r"(r[3]) : "r"(addr));
}
__device__ __forceinline__ void ldsm2(uint32_t* r, uint32_t addr) {
    asm volatile("ldmatrix.sync.aligned.m8n8.x2.shared.b16 {%0,%1}, [%2];"
        : "=r"(r[0]), "=r"(r[1]) : "r"(addr));
}
__device__ __forceinline__ void mma16816(float* d, const uint32_t* a, const uint32_t* b) {
    asm volatile("mma.sync.aligned.m16n8k16.row.col.f32.f16.f16.f32 "
        "{%0,%1,%2,%3}, {%4,%5,%6,%7}, {%8,%9}, {%0,%1,%2,%3};"
        : "+f"(d[0]), "+f"(d[1]), "+f"(d[2]), "+f"(d[3])
        : "r"(a[0]), "r"(a[1]), "r"(a[2]), "r"(a[3]), "r"(b[0]), "r"(b[1]));
}

__device__ __forceinline__ float sigmoidf_(float x) { return 1.f / (1.f + expf(-x)); }

struct Offs5 { uint32_t a0, a1, b0, b1, b2; };
__device__ __forceinline__ Offs5 make_offs5(int wm, int wn, int lane) {
    Offs5 o;
    const uint32_t sa = (lane >> 4) << 4;
    const uint32_t sb = ((lane >> 3) & 1) << 4;
    o.a0 = swz(wm + (lane & 15), sa);
    o.a1 = swz(wm + 16 + (lane & 15), sa);
    o.b0 = swz(wn + ((lane >> 4) << 3) + (lane & 7), sb);
    o.b1 = swz(wn + 16 + ((lane >> 4) << 3) + (lane & 7), sb);
    o.b2 = swz(wn + 32 + (lane & 7), sb);
    return o;
}
struct Offs6 { uint32_t a0, a1, b0, b1, b2; };
__device__ __forceinline__ Offs6 make_offs6(int wm, int wn, int lane) {
    Offs6 o;
    const uint32_t sa = (lane >> 4) << 4;
    const uint32_t sb = ((lane >> 3) & 1) << 4;
    o.a0 = swz(wm + (lane & 15), sa);
    o.a1 = swz(wm + 16 + (lane & 15), sa);
    o.b0 = swz(wn + ((lane >> 4) << 3) + (lane & 7), sb);
    o.b1 = swz(wn + 16 + ((lane >> 4) << 3) + (lane & 7), sb);
    o.b2 = swz(wn + 32 + ((lane >> 4) << 3) + (lane & 7), sb);
    return o;
}

__device__ __forceinline__ void chunk_mma5(uint32_t abuf, uint32_t bbuf,
                                           const Offs5& o, float acc[2][5][4]) {
#pragma unroll
    for (int k16 = 0; k16 < 4; ++k16) {
        const uint32_t kx = (uint32_t)k16 << 5;
        uint32_t a[2][4], b[5][2], r0[4], r1[4];
        ldsm4(a[0], abuf + (o.a0 ^ kx));
        ldsm4(a[1], abuf + (o.a1 ^ kx));
        ldsm4(r0, bbuf + (o.b0 ^ kx));
        ldsm4(r1, bbuf + (o.b1 ^ kx));
        ldsm2(b[4], bbuf + (o.b2 ^ kx));
        b[0][0] = r0[0]; b[0][1] = r0[1]; b[1][0] = r0[2]; b[1][1] = r0[3];
        b[2][0] = r1[0]; b[2][1] = r1[1]; b[3][0] = r1[2]; b[3][1] = r1[3];
#pragma unroll
        for (int mt = 0; mt < 2; ++mt)
#pragma unroll
            for (int nt = 0; nt < 5; ++nt)
                mma16816(acc[mt][nt], a[mt], b[nt]);
    }
}

__device__ __forceinline__ void chunk_mma6(uint32_t abuf, uint32_t bbuf,
                                           const Offs6& o, float acc[2][6][4]) {
#pragma unroll
    for (int k16 = 0; k16 < 4; ++k16) {
        const uint32_t kx = (uint32_t)k16 << 5;
        uint32_t a[2][4], b[6][2], r0[4], r1[4], r2[4];
        ldsm4(a[0], abuf + (o.a0 ^ kx));
        ldsm4(a[1], abuf + (o.a1 ^ kx));
        ldsm4(r0, bbuf + (o.b0 ^ kx));
        ldsm4(r1, bbuf + (o.b1 ^ kx));
        ldsm4(r2, bbuf + (o.b2 ^ kx));
        b[0][0] = r0[0]; b[0][1] = r0[1]; b[1][0] = r0[2]; b[1][1] = r0[3];
        b[2][0] = r1[0]; b[2][1] = r1[1]; b[3][0] = r1[2]; b[3][1] = r1[3];
        b[4][0] = r2[0]; b[4][1] = r2[1]; b[5][0] = r2[2]; b[5][1] = r2[3];
#pragma unroll
        for (int mt = 0; mt < 2; ++mt)
#pragma unroll
            for (int nt = 0; nt < 6; ++nt)
                mma16816(acc[mt][nt], a[mt], b[nt]);
    }
}

// ---------------- pack kernels ----------------
__global__ void conv_emb_kernel(const float* __restrict__ emb) {
    int idx = blockIdx.x * blockDim.x + threadIdx.x;
    int stride = gridDim.x * blockDim.x;
    const int total4 = (NN * H) / 4;
    for (int i = idx; i < total4; i += stride) {
        float4 v = reinterpret_cast<const float4*>(emb)[i];
        __half hh[4];
        hh[0] = __float2half(v.x);
        hh[1] = __float2half(v.y);
        hh[2] = __float2half(v.z);
        hh[3] = __float2half(v.w);
        reinterpret_cast<uint2*>(g_e)[i] = *reinterpret_cast<uint2*>(hh);
    }
}

__global__ void pack_w_kernel(
    const float* __restrict__ Wi, const float* __restrict__ bi, const float* __restrict__ Ui,
    const float* __restrict__ Wo, const float* __restrict__ bo, const float* __restrict__ Uo,
    const float* __restrict__ Wu, const float* __restrict__ bu, const float* __restrict__ Uu,
    const float* __restrict__ Wf, const float* __restrict__ bf, const float* __restrict__ Uf)
{
    int idx = blockIdx.x * blockDim.x + threadIdx.x;
    int stride = gridDim.x * blockDim.x;
    if (idx < NCOL) {
        int j = idx / 5, g = idx % 5;
        g_bias[idx] = (g == 0) ? bi[j] : (g == 1) ? bo[j] : (g == 2) ? bu[j] : bf[j];
    }
    for (int e = idx; e < NCOL * KIN; e += stride) {
        int col = e / KIN;
        int k   = e - col * KIN;
        int j = col / 5, g = col % 5;
        float v = 0.f;
        if (k < H) {
            const float* W = (g == 0) ? Wi : (g == 1) ? Wo : (g == 2) ? Wu : Wf;
            v = W[j * H + k];
        } else if (k < 2 * H) {
            int kk = k - H;
            if      (g == 0) v = Ui[j * H + kk];
            else if (g == 1) v = Uo[j * H + kk];
            else if (g == 2) v = Uu[j * H + kk];
            else if (g == 3) v = Uf[j * H + kk];
        } else {
            int kk = k - 2 * H;
            if      (g == 0) v = Ui[H * H + j * H + kk];
            else if (g == 1) v = Uo[H * H + j * H + kk];
            else if (g == 2) v = Uu[H * H + j * H + kk];
            else if (g == 4) v = Uf[H * H + j * H + kk];
        }
        g_B[e] = __float2half(v);
    }
    for (int e = idx; e < NCOL3 * H; e += stride) {
        int col = e / H;
        int k   = e - col * H;
        int j = col / 3, g = col % 3;
        const float* W = (g == 0) ? Wi : (g == 1) ? Wo : Wu;
        g_B3[e] = __float2half(W[j * H + k]);
    }
}

// ---------------- internal level kernel: 128 x 80, KT=64, 2-stage, 3 CTAs/SM ----------------
// K = 768, 12 chunks: sec = c>>2 (emb | c1h | c2h), kof = (c&3)*64.
__global__ void __launch_bounds__(256, 3) hmma_level_kernel(
    int start, int n, float* __restrict__ out)
{
    extern __shared__ char smem[];
    const uint32_t sbase = smem_to_u32(smem);

    const int t    = threadIdx.x;
    const int lane = t & 31;
    const int wid  = t >> 5;
    const int cb   = blockIdx.x;
    const int m0   = blockIdx.y * 128;
    const int gn0  = start + m0;
    const int col0 = cb * 80;

    constexpr int NCH = 12;

    const __half* e_p  = g_e + (size_t)gn0 * H;
    const __half* c1h  = g_h + (size_t)(2 * gn0 + 1) * H;
    const __half* c2h  = g_h + (size_t)(2 * gn0 + 2) * H;

    const int r0 = t >> 3;
    const uint32_t seg8 = (uint32_t)(t & 7) * 8;
    const uint32_t swz0 = swz(r0, (uint32_t)(t & 7) * 16);
    const uint32_t r0H  = (uint32_t)r0 * H;
    const uint32_t r0K  = (uint32_t)r0 * KIN;
    const bool bTail = (t < 128);

    float acc[2][5][4];
#pragma unroll
    for (int mt = 0; mt < 2; ++mt)
#pragma unroll
        for (int nt = 0; nt < 5; ++nt)
#pragma unroll
            for (int r = 0; r < 4; ++r) acc[mt][nt][r] = 0.f;

    auto load_chunk = [&](int c, int st) {
        const int sec = c >> 2;
        const uint32_t kof = (uint32_t)(c & 3) << 6;
        const __half* ab = (sec == 0) ? e_p : (sec == 1) ? c1h : c2h;
        const uint32_t astep = (sec == 0) ? 32u * H : 64u * H;
        const __half* asrc = ab + ((sec == 0) ? r0H : 2 * r0H) + kof + seg8;
        const __half* bsrc = g_B + (size_t)col0 * KIN + c * 64 + r0K + seg8;
        const uint32_t adst = sbase + st * ASTG + swz0;
        const uint32_t bdst = sbase + OFF_BS_MAIN + st * BSTG + swz0;
        cpasync16(adst +     0, asrc);
        cpasync16(adst +  4096, asrc + astep);
        cpasync16(adst +  8192, asrc + 2 * astep);
        cpasync16(adst + 12288, asrc + 3 * astep);
        cpasync16(bdst +     0, bsrc);
        cpasync16(bdst +  4096, bsrc + 32 * KIN);
        if (bTail) cpasync16(bdst + 8192, bsrc + 64 * KIN);
        CP_COMMIT();
    };

    load_chunk(0, 0);

    const int wm = (wid & 3) * 32;
    const int wn = (wid >> 2) * 40;
    const Offs5 offs = make_offs5(wm, wn, lane);

    for (int c = 0; c < NCH; ++c) {
        const int st = c & 1;
        CP_WAIT(0);
        __syncthreads();
        if (c + 1 < NCH) load_chunk(c + 1, st ^ 1);
        chunk_mma5(sbase + st * ASTG, sbase + OFF_BS_MAIN + st * BSTG, offs, acc);
    }
    __syncthreads();

    float* Cs = reinterpret_cast<float*>(smem);     // [128][84]
#pragma unroll
    for (int mt = 0; mt < 2; ++mt)
#pragma unroll
        for (int nt = 0; nt < 5; ++nt) {
            int m  = wm + mt * 16 + (lane >> 2);
            int nn = wn + nt * 8 + (lane & 3) * 2;
            Cs[m * 84 + nn]           = acc[mt][nt][0];
            Cs[m * 84 + nn + 1]       = acc[mt][nt][1];
            Cs[(m + 8) * 84 + nn]     = acc[mt][nt][2];
            Cs[(m + 8) * 84 + nn + 1] = acc[mt][nt][3];
        }
    __syncthreads();

#pragma unroll
    for (int pass = 0; pass < 8; ++pass) {
        const int task = t + pass * 256;
        const int m = task >> 4;
        const int u = task & 15;
        if (m0 + m >= n) continue;
        const int gn = gn0 + m;
        const int j  = cb * 16 + u;

        const float* cp = &Cs[m * 84 + u * 5];
        float zi = cp[0] + g_bias[j * 5 + 0];
        float zo = cp[1] + g_bias[j * 5 + 1];
        float zu = cp[2] + g_bias[j * 5 + 2];
        float zf0 = cp[3] + g_bias[j * 5 + 3];
        float zf1 = cp[4] + g_bias[j * 5 + 4];
        float vi = sigmoidf_(zi);
        float vo = sigmoidf_(zo);
        float vu = tanhf(zu);
        float cv = vi * vu
                 + sigmoidf_(zf0) * g_c[(size_t)(2 * gn + 1) * H + j]
                 + sigmoidf_(zf1) * g_c[(size_t)(2 * gn + 2) * H + j];
        float h = vo * tanhf(cv);
        g_h[(size_t)gn * H + j] = __float2half(h);
        g_c[(size_t)gn * H + j] = cv;
        if (out != nullptr && gn == 0) {
            out[j]     = h;
            out[H + j] = cv;
        }
    }
}

// ---------------- leaf kernel: 128 nodes x 96 cols (32 units x 3 gates), K=256 ----------------
__global__ void __launch_bounds__(256, 3) leaf_kernel(int start, int n)
{
    extern __shared__ char smem[];
    const uint32_t sbase = smem_to_u32(smem);

    const int t    = threadIdx.x;
    const int lane = t & 31;
    const int wid  = t >> 5;
    const int cb   = blockIdx.x;
    const int m0   = blockIdx.y * 128;
    const int gn0  = start + m0;
    const int col0 = cb * 96;

    constexpr int NCH = 4;

    const __half* e_p = g_e + (size_t)gn0 * H;

    const int r0 = t >> 3;
    const uint32_t seg8 = (uint32_t)(t & 7) * 8;
    const uint32_t swz0 = swz(r0, (uint32_t)(t & 7) * 16);
    const uint32_t r0H  = (uint32_t)r0 * H;

    float acc[2][6][4];
#pragma unroll
    for (int mt = 0; mt < 2; ++mt)
#pragma unroll
        for (int nt = 0; nt < 6; ++nt)
#pragma unroll
            for (int r = 0; r < 4; ++r) acc[mt][nt][r] = 0.f;

    auto load_chunk = [&](int c, int st) {
        const uint32_t kof = (uint32_t)c << 6;
        const __half* asrc = e_p + r0H + kof + seg8;
        const __half* bsrc = g_B3 + (size_t)col0 * H + kof + r0H + seg8;
        const uint32_t adst = sbase + st * ASTG + swz0;
        const uint32_t bdst = sbase + OFF_BS_LEAF + st * B3STG + swz0;
        cpasync16(adst +     0, asrc);
        cpasync16(adst +  4096, asrc + 32 * H);
        cpasync16(adst +  8192, asrc + 64 * H);
        cpasync16(adst + 12288, asrc + 96 * H);
        cpasync16(bdst +     0, bsrc);
        cpasync16(bdst +  4096, bsrc + 32 * H);
        cpasync16(bdst +  8192, bsrc + 64 * H);
        CP_COMMIT();
    };

    load_chunk(0, 0);

    const int wm = (wid & 3) * 32;
    const int wn = (wid >> 2) * 48;
    const Offs6 offs = make_offs6(wm, wn, lane);

    for (int c = 0; c < NCH; ++c) {
        const int st = c & 1;
        CP_WAIT(0);
        __syncthreads();
        if (c + 1 < NCH) load_chunk(c + 1, st ^ 1);
        chunk_mma6(sbase + st * ASTG, sbase + OFF_BS_LEAF + st * B3STG, offs, acc);
    }
    __syncthreads();

    float* Cs = reinterpret_cast<float*>(smem);     // [128][100]
#pragma unroll
    for (int mt = 0; mt < 2; ++mt)
#pragma unroll
        for (int nt = 0; nt < 6; ++nt) {
            int m  = wm + mt * 16 + (lane >> 2);
            int nn = wn + nt * 8 + (lane & 3) * 2;
            Cs[m * 100 + nn]           = acc[mt][nt][0];
            Cs[m * 100 + nn + 1]       = acc[mt][nt][1];
            Cs[(m + 8) * 100 + nn]     = acc[mt][nt][2];
            Cs[(m + 8) * 100 + nn + 1] = acc[mt][nt][3];
        }
    __syncthreads();

#pragma unroll
    for (int pass = 0; pass < 16; ++pass) {
        const int task = t + pass * 256;
        const int m = task >> 5;
        const int u = task & 31;
        if (m0 + m >= n) continue;
        const int gn = gn0 + m;
        const int j  = cb * 32 + u;

        const float* cp = &Cs[m * 100 + u * 3];
        float zi = cp[0] + g_bias[j * 5 + 0];
        float zo = cp[1] + g_bias[j * 5 + 1];
        float zu = cp[2] + g_bias[j * 5 + 2];
        float vi = sigmoidf_(zi);
        float vo = sigmoidf_(zo);
        float vu = tanhf(zu);
        float cv = vi * vu;
        float h = vo * tanhf(cv);
        g_h[(size_t)gn * H + j] = __float2half(h);
        g_c[(size_t)gn * H + j] = cv;
    }
}

// ---------------- small-level kernel: split-K x4, M tile = 32, 2 CTAs/SM ----------------
// 12 chunks / 4 slices = 3 per slice. Chunk c: sec = c>>2, kof = (c&3)*64.
__global__ void __launch_bounds__(256, 2) smallk_kernel(int start, int n, float* __restrict__ out)
{
    extern __shared__ char smem[];
    const uint32_t sbase = smem_to_u32(smem);

    const int t    = threadIdx.x;
    const int lane = t & 31;
    const int wid  = t >> 5;
    const int cb   = blockIdx.x;
    const int m0   = blockIdx.y * 32;
    const int gn0  = start + m0;
    const int col0 = cb * 80;

    const int ks = wid >> 1;
    const int wn = (wid & 1) * 40;

    constexpr int PER = 3;                // chunks per slice (12/4)

    float acc[2][5][4];
#pragma unroll
    for (int mt = 0; mt < 2; ++mt)
#pragma unroll
        for (int nt = 0; nt < 5; ++nt)
#pragma unroll
            for (int r = 0; r < 4; ++r) acc[mt][nt][r] = 0.f;

    auto load_step = [&](int step, int st) {
#pragma unroll
        for (int i = 0; i < 14; ++i) {
            int idx = t + i * 256;
            int sl  = idx / 896;
            int rem = idx - sl * 896;
            int c   = sl * PER + step;      // 0..11
            uint32_t sbuf = sbase + (sl * 2 + st) * SLST;
            const int sec = c >> 2;
            const int kof = (c & 3) << 6;
            const __half* abase;
            int astride;
            if (sec == 0)      { abase = g_e + (size_t)gn0 * H + kof;              astride = H; }
            else if (sec == 1) { abase = g_h + (size_t)(2 * gn0 + 1) * H + kof;    astride = 2 * H; }
            else               { abase = g_h + (size_t)(2 * gn0 + 2) * H + kof;    astride = 2 * H; }
            if (rem < 256) {
                int row = rem >> 3, seg = rem & 7;
                cpasync16(sbuf + swz(row, seg * 16),
                          abase + (size_t)row * astride + seg * 8);
            } else {
                int r2 = rem - 256;
                int row = r2 >> 3, seg = r2 & 7;
                const __half* bbase = g_B + (size_t)col0 * KIN + c * 64;
                cpasync16(sbuf + 32 * 128 + swz(row, seg * 16),
                          bbase + (size_t)row * KIN + seg * 8);
            }
        }
        CP_COMMIT();
    };

    load_step(0, 0);

    const Offs5 offs = make_offs5(0, wn, lane);

    for (int step = 0; step < PER; ++step) {
        const int st = step & 1;
        CP_WAIT(0);
        __syncthreads();
        if (step + 1 < PER) load_step(step + 1, st ^ 1);
        const uint32_t abuf = sbase + (ks * 2 + st) * SLST;
        chunk_mma5(abuf, abuf + 32 * 128, offs, acc);
    }
    __syncthreads();

    float* Cp = reinterpret_cast<float*>(smem);   // [4][32][84]
#pragma unroll
    for (int mt = 0; mt < 2; ++mt)
#pragma unroll
        for (int nt = 0; nt < 5; ++nt) {
            int m  = mt * 16 + (lane >> 2);
            int nn = wn + nt * 8 + (lane & 3) * 2;
            float* dst = Cp + ks * (32 * 84);
            dst[m * 84 + nn]           = acc[mt][nt][0];
            dst[m * 84 + nn + 1]       = acc[mt][nt][1];
            dst[(m + 8) * 84 + nn]     = acc[mt][nt][2];
            dst[(m + 8) * 84 + nn + 1] = acc[mt][nt][3];
        }
    __syncthreads();

#pragma unroll
    for (int pass = 0; pass < 2; ++pass) {
        const int task = t + pass * 256;
        const int m = task >> 4;
        const int u = task & 15;
        if (m0 + m >= n) continue;
        const int gn = gn0 + m;
        const int j  = cb * 16 + u;

        float z[5];
#pragma unroll
        for (int g = 0; g < 5; ++g) {
            float s = g_bias[j * 5 + g];
#pragma unroll
            for (int sl = 0; sl < 4; ++sl)
                s += Cp[sl * (32 * 84) + m * 84 + u * 5 + g];
            z[g] = s;
        }
        float vi = sigmoidf_(z[0]);
        float vo = sigmoidf_(z[1]);
        float vu = tanhf(z[2]);
        float cv = vi * vu
                 + sigmoidf_(z[3]) * g_c[(size_t)(2 * gn + 1) * H + j]
                 + sigmoidf_(z[4]) * g_c[(size_t)(2 * gn + 2) * H + j];
        float h = vo * tanhf(cv);
        g_h[(size_t)gn * H + j] = __float2half(h);
        g_c[(size_t)gn * H + j] = cv;
        if (out != nullptr && gn == 0) {
            out[j]     = h;
            out[H + j] = cv;
        }
    }
}

// ---------------- host launcher ----------------
extern "C" void kernel_launch(void* const* d_in, const int* in_sizes, int n_in,
                              void* d_out, int out_size)
{
    const float* emb = (const float*)d_in[0];
    const float* Wi  = (const float*)d_in[1];
    const float* bi  = (const float*)d_in[2];
    const float* Ui  = (const float*)d_in[3];
    const float* Wo  = (const float*)d_in[4];
    const float* bo  = (const float*)d_in[5];
    const float* Uo  = (const float*)d_in[6];
    const float* Wu  = (const float*)d_in[7];
    const float* bu  = (const float*)d_in[8];
    const float* Uu  = (const float*)d_in[9];
    const float* Wf  = (const float*)d_in[10];
    const float* bf  = (const float*)d_in[11];
    const float* Uf  = (const float*)d_in[12];

    cudaFuncSetAttribute(hmma_level_kernel, cudaFuncAttributeMaxDynamicSharedMemorySize, SMEM_MAIN);
    cudaFuncSetAttribute(leaf_kernel,       cudaFuncAttributeMaxDynamicSharedMemorySize, SMEM_LEAF);
    cudaFuncSetAttribute(smallk_kernel,     cudaFuncAttributeMaxDynamicSharedMemorySize, SMEM_SMALL);

    conv_emb_kernel<<<2048, 256>>>(emb);
    pack_w_kernel<<<1024, 256>>>(Wi, bi, Ui, Wo, bo, Uo, Wu, bu, Uu, Wf, bf, Uf);

    // leaves: level 15, n = 32768, 3 gates only
    {
        int n = 1 << (DEPTH - 1);
        int start = n - 1;
        dim3 grid(8, n / 128);
        leaf_kernel<<<grid, 256, SMEM_LEAF>>>(start, n);
    }
    // internal levels bottom-up
    for (int l = DEPTH - 2; l >= 0; --l) {
        int n = 1 << l;
        int start = n - 1;
        float* outp = (l == 0) ? (float*)d_out : nullptr;
        if (n >= 1024) {
            dim3 grid(16, n / 128);
            hmma_level_kernel<<<grid, 256, SMEM_MAIN>>>(start, n, outp);
        } else {
            dim3 grid(16, (n + 31) / 32);
            smallk_kernel<<<grid, 256, SMEM_SMALL>>>(start, n, outp);
        }
    }
}